// round 12
// baseline (speedup 1.0000x reference)
#include <cuda_runtime.h>
#include <cstdint>
#include <cstddef>

#define NB    4
#define NSRC  16384
#define NTGT  4096
#define KNN   32
#define FULLM 0xffffffffu

// spatial grid (h = 0.25: d<=1 box ~440 candidates in the core vs ~1500 at G=32)
#define G     48
#define NCELL (G*G*G)
#define LB    6.0f
#define GH    0.25f
#define INVH  (1.0f/GH)

// Output layout (flattened concat, all float32):
#define OFF_PATCH 0
#define OFF_IDX   1572864
#define OFF_SIZE  2621440
#define OFF_RAD   2637824
#define OFF_DIST  2637828

// __device__ scratch (no allocations allowed)
__device__ int    g_cnt[NB * NCELL];
__device__ int    g_cur[NB * NCELL];
__device__ int    g_start[NB * (NCELL + 1)];
__device__ float4 g_pts[NB * NSRC];   // (x, y, z, sumsq), cell-sorted
__device__ int    g_pidx[NB * NSRC];  // original within-batch index

__device__ __forceinline__ int cellcoord(float v) {
    int c = (int)floorf((v + LB) * INVH);
    return min(G - 1, max(0, c));
}

__global__ void k_zero() {
    int i = blockIdx.x * blockDim.x + threadIdx.x;
    if (i < NB * NCELL) g_cnt[i] = 0;
}

__global__ void k_count(const float* __restrict__ src) {
    int i = blockIdx.x * blockDim.x + threadIdx.x;
    if (i >= NB * NSRC) return;
    int b = i / NSRC;
    float x = src[3 * i], y = src[3 * i + 1], z = src[3 * i + 2];
    int cell = (cellcoord(z) * G + cellcoord(y)) * G + cellcoord(x);
    atomicAdd(&g_cnt[b * NCELL + cell], 1);
}

#define CPT (NCELL / 1024)
__global__ void k_scan() {
    __shared__ int sm[1024];
    int b = blockIdx.x, t = threadIdx.x;
    const int* cnt = g_cnt + b * NCELL;
    int* start = g_start + b * (NCELL + 1);
    int* cur   = g_cur + b * NCELL;
    int s = 0;
    #pragma unroll
    for (int c = 0; c < CPT; c++) s += cnt[t * CPT + c];
    sm[t] = s; __syncthreads();
    for (int off = 1; off < 1024; off <<= 1) {
        int v = (t >= off) ? sm[t - off] : 0;
        __syncthreads();
        sm[t] += v;
        __syncthreads();
    }
    int run = sm[t] - s;
    #pragma unroll
    for (int c = 0; c < CPT; c++) {
        int id = t * CPT + c;
        start[id] = run; cur[id] = run;
        run += cnt[id];
    }
    if (t == 1023) start[NCELL] = NSRC;
}

__global__ void k_scatter(const float* __restrict__ src) {
    int i = blockIdx.x * blockDim.x + threadIdx.x;
    if (i >= NB * NSRC) return;
    int b = i / NSRC;
    float x = src[3 * i], y = src[3 * i + 1], z = src[3 * i + 2];
    int cell = (cellcoord(z) * G + cellcoord(y)) * G + cellcoord(x);
    int pos = atomicAdd(&g_cur[b * NCELL + cell], 1);
    float ss = __fadd_rn(__fadd_rn(__fmul_rn(x, x), __fmul_rn(y, y)), __fmul_rn(z, z));
    g_pts[b * NSRC + pos]  = make_float4(x, y, z, ss);
    g_pidx[b * NSRC + pos] = i - b * NSRC;
}

// One warp per target. Exact KNN via expanding Chebyshev shells.
// Top-K warp-sorted ascending under lexicographic (value, index) order
// == jax top_k tie-break; min-32-of-union is scan-order invariant.
__global__ __launch_bounds__(256) void k_query(const float* __restrict__ src,
                                               const float* __restrict__ tgt,
                                               float* __restrict__ out) {
    __shared__ int s_p0 [8][32];
    __shared__ int s_pre[8][32];

    const int w    = threadIdx.x >> 5;
    const int lane = threadIdx.x & 31;
    const int tg   = blockIdx.x * 8 + w;
    const int b    = tg / NTGT;

    const float px = tgt[3 * tg], py = tgt[3 * tg + 1], pz = tgt[3 * tg + 2];
    const float tt = __fadd_rn(__fadd_rn(__fmul_rn(px, px), __fmul_rn(py, py)),
                               __fmul_rn(pz, pz));

    const int cx = cellcoord(px), cy = cellcoord(py), cz = cellcoord(pz);
    float ex = fmaxf(fmaxf(-LB - px, px - LB), 0.0f);
    float ey = fmaxf(fmaxf(-LB - py, py - LB), 0.0f);
    float ez = fmaxf(fmaxf(-LB - pz, pz - LB), 0.0f);
    const float e = sqrtf(ex * ex + ey * ey + ez * ez);

    const float INF  = __int_as_float(0x7f800000);
    const int   IMAX = 0x7fffffff;
    float lv = INF; int li = IMAX;
    float thr_v = INF; int thr_i = IMAX;
    bool filled = false;

    const int*    cstart = g_start + b * (NCELL + 1);
    const float4* pts    = g_pts + b * NSRC;
    const int*    pidx   = g_pidx + b * NSRC;

    const int dmax = max(max(max(cx, G - 1 - cx), max(cy, G - 1 - cy)),
                         max(cz, G - 1 - cz));

    // ascending-lex bitonic sort of one (value,index) per lane
    auto sort32 = [&](float& v, int& ix) {
        #pragma unroll
        for (int kk = 2; kk <= 32; kk <<= 1) {
            #pragma unroll
            for (int j = kk >> 1; j > 0; j >>= 1) {
                const float ov = __shfl_xor_sync(FULLM, v, j);
                const int   oi = __shfl_xor_sync(FULLM, ix, j);
                const bool dirAsc = ((lane & kk) == 0);
                const bool otherLess = (ov < v) || (ov == v && oi < ix);
                const bool lower = (lane & j) == 0;
                const bool keepOther = lower ? (dirAsc ? otherLess : !otherLess)
                                             : (dirAsc ? !otherLess : otherLess);
                if (keepOther) { v = ov; ix = oi; }
            }
        }
    };

    for (int d = 0;; ++d) {
        const int nseg = (d == 0) ? 1 : (8 * d + 2 * (2 * d - 1) * (2 * d - 1));
        for (int bk = 0; bk < nseg; bk += 32) {
            // ---- lane-parallel segment ranges ----
            const int k = bk + lane;
            bool valid = (k < nseg);
            int zc = cz, yc = cy, x0 = cx, x1 = cx;
            if (valid && d > 0) {
                if (k < 8 * d) {                 // perimeter rows (full x span)
                    const int side = k / (2 * d), off = k % (2 * d);
                    int zo, yo;
                    if      (side == 0) { zo = -d;       yo = -d + off; }
                    else if (side == 1) { yo =  d;       zo = -d + off; }
                    else if (side == 2) { zo =  d;       yo =  d - off; }
                    else                { yo = -d;       zo =  d - off; }
                    zc = cz + zo; yc = cy + yo;
                    x0 = max(cx - d, 0); x1 = min(cx + d, G - 1);
                } else {                          // inner rows: 2 single cells
                    const int k2 = k - 8 * d;
                    const int w2 = 2 * d - 1;
                    const int r = k2 >> 1, side = k2 & 1;
                    zc = cz + (-d + 1 + r / w2);
                    yc = cy + (-d + 1 + r % w2);
                    const int x = side ? (cx + d) : (cx - d);
                    x0 = x1 = x;
                    if (x < 0 || x >= G) valid = false;
                }
                if (zc < 0 || zc >= G || yc < 0 || yc >= G) valid = false;
            }
            int p0 = 0, len = 0;
            if (valid) {
                const int cb = (zc * G + yc) * G;
                p0  = cstart[cb + x0];
                len = cstart[cb + x1 + 1] - p0;
            }
            // exclusive warp scan of len
            int pre = len;
            #pragma unroll
            for (int off = 1; off < 32; off <<= 1) {
                int n = __shfl_up_sync(FULLM, pre, off);
                if (lane >= off) pre += n;
            }
            const int total = __shfl_sync(FULLM, pre, 31);
            pre -= len;
            s_p0 [w][lane] = p0;
            s_pre[w][lane] = pre;
            __syncwarp(FULLM);
            if (total == 0) continue;

            // ---- flat candidate stream ----
            for (int base = 0; base < total; base += 32) {
                const int pos = base + lane;
                float sqv = INF; int jj = IMAX;
                if (pos < total) {
                    int lo = 0;              // max s with pre[s] <= pos
                    #pragma unroll
                    for (int step = 16; step; step >>= 1) {
                        const int cand = lo + step;
                        if (cand < 32 && s_pre[w][cand] <= pos) lo = cand;
                    }
                    const int ii = s_p0[w][lo] + (pos - s_pre[w][lo]);
                    const float4 S = pts[ii];
                    jj = pidx[ii];
                    float dot = __fmaf_rn(pz, S.z,
                                 __fmaf_rn(py, S.y, __fmul_rn(px, S.x)));
                    sqv = __fadd_rn(__fsub_rn(tt, __fmul_rn(2.0f, dot)), S.w);
                }

                if (filled) {
                    const bool acc = (sqv < thr_v) || (sqv == thr_v && jj < thr_i);
                    unsigned ball = __ballot_sync(FULLM, acc);
                    const int nacc = __popc(ball);
                    if (nacc == 0) continue;
                    if (nacc < 8) {
                        // serial insertion (cheap for sparse accepts)
                        do {
                            const int   sl = __ffs(ball) - 1;
                            ball &= ball - 1;
                            const float nv = __shfl_sync(FULLM, sqv, sl);
                            const int   nj = __shfl_sync(FULLM, jj,  sl);
                            const unsigned le =
                                __ballot_sync(FULLM, (lv < nv) || (lv == nv && li < nj));
                            const int ppos = __popc(le);
                            if (ppos < 32) {
                                const float pv = __shfl_up_sync(FULLM, lv, 1);
                                const int   pj = __shfl_up_sync(FULLM, li, 1);
                                if (lane > ppos)       { lv = pv; li = pj; }
                                else if (lane == ppos) { lv = nv; li = nj; }
                            }
                        } while (ball);
                        thr_v = __shfl_sync(FULLM, lv, 31);
                        thr_i = __shfl_sync(FULLM, li, 31);
                        continue;
                    }
                    // dense accepts: batch sort + bitonic merge (constant depth)
                    if (!acc) { sqv = INF; jj = IMAX; }
                    sort32(sqv, jj);
                    // concat(lv asc, batch desc) is bitonic; halver keeps 32 mins
                    const float bv = __shfl_sync(FULLM, sqv, 31 - lane);
                    const int   bi = __shfl_sync(FULLM, jj,  31 - lane);
                    const bool keepB = (bv < lv) || (bv == lv && bi < li);
                    float cv = keepB ? bv : lv;
                    int   ci = keepB ? bi : li;
                    // 5-stage bitonic merge, ascending lex
                    #pragma unroll
                    for (int j = 16; j; j >>= 1) {
                        const float ov = __shfl_xor_sync(FULLM, cv, j);
                        const int   oi = __shfl_xor_sync(FULLM, ci, j);
                        const bool otherLess = (ov < cv) || (ov == cv && oi < ci);
                        const bool lower = (lane & j) == 0;
                        if (lower ? otherLess : !otherLess) { cv = ov; ci = oi; }
                    }
                    lv = cv; li = ci;
                    thr_v = __shfl_sync(FULLM, lv, 31);
                    thr_i = __shfl_sync(FULLM, li, 31);
                } else {
                    // initial fill: sort the first batch, take as list
                    sort32(sqv, jj);
                    lv = sqv; li = jj;
                    thr_v = __shfl_sync(FULLM, lv, 31);
                    thr_i = __shfl_sync(FULLM, li, 31);
                    filled = true;
                }
            }
        }
        const float dm = __fmaf_rn((float)d, GH, -e);
        if (dm > 0.0f && thr_v < dm * dm) break;   // strict: protects index ties
        if (d >= dmax) break;
    }

    // ---- outputs ----
    const float rad  = 0.2f;
    const float rad2 = __fmul_rn(rad, rad);
    const bool  mask = (rad2 >= lv);

    float gx = 0.0f, gy = 0.0f, gz = 0.0f;
    if (mask) {
        const float* sp = src + (size_t)(b * NSRC + li) * 3;
        gx = __fdiv_rn(sp[0], rad);
        gy = __fdiv_rn(sp[1], rad);
        gz = __fdiv_rn(sp[2], rad);
    }
    const float tdx = __fdiv_rn(px, rad);
    const float tdy = __fdiv_rn(py, rad);
    const float tdz = __fdiv_rn(pz, rad);

    const size_t ee = (size_t)tg * KNN + lane;

    float* patches = out + OFF_PATCH;
    patches[3 * ee + 0] = __fsub_rn(gx, tdx);
    patches[3 * ee + 1] = __fsub_rn(gy, tdy);
    patches[3 * ee + 2] = __fsub_rn(gz, tdz);

    float* idxf = out + OFF_IDX;
    idxf[2 * ee + 0] = (float)b;
    idxf[2 * ee + 1] = (float)(mask ? li : -1);

    float* pdist = out + OFF_DIST;
    pdist[ee] = __fdiv_rn(__fsqrt_rn(fmaxf(lv, 1e-9f)), rad);

    const unsigned mball = __ballot_sync(FULLM, mask);
    if (lane == 0) {
        float* psize = out + OFF_SIZE;
        psize[tg] = (float)__popc(mball);
    }

    if (blockIdx.x == 0 && threadIdx.x < NB) {
        float* prad = out + OFF_RAD;
        prad[threadIdx.x] = rad;
    }
}

extern "C" void kernel_launch(void* const* d_in, const int* in_sizes, int n_in,
                              void* d_out, int out_size) {
    const float* src = (const float*)d_in[0];
    const float* tgt = (const float*)d_in[1];
    if (n_in >= 2 && in_sizes[0] == NB * NTGT * 3 && in_sizes[1] == NB * NSRC * 3) {
        src = (const float*)d_in[1];
        tgt = (const float*)d_in[0];
    }
    float* out = (float*)d_out;

    k_zero   <<<(NB * NCELL + 255) / 256, 256>>>();
    k_count  <<<(NB * NSRC + 255) / 256, 256>>>(src);
    k_scan   <<<NB, 1024>>>();
    k_scatter<<<(NB * NSRC + 255) / 256, 256>>>(src);
    k_query  <<<(NB * NTGT) / 8, 256>>>(src, tgt, out);
}

// round 13
// speedup vs baseline: 1.6033x; 1.6033x over previous
#include <cuda_runtime.h>
#include <cstdint>
#include <cstddef>

#define NB    4
#define NSRC  16384
#define NTGT  4096
#define KNN   32
#define FULLM 0xffffffffu

// spatial grid
#define G     32
#define NCELL (G*G*G)
#define LB    6.0f
#define GH    0.375f
#define INVH  (1.0f/GH)

// Output layout (flattened concat, all float32):
#define OFF_PATCH 0
#define OFF_IDX   1572864
#define OFF_SIZE  2621440
#define OFF_RAD   2637824
#define OFF_DIST  2637828

// __device__ scratch (no allocations allowed)
__device__ int    g_cnt[NB * NCELL];
__device__ int    g_cur[NB * NCELL];
__device__ int    g_start[NB * (NCELL + 1)];
__device__ float4 g_pts[NB * NSRC];   // (x, y, z, sumsq), cell-sorted
__device__ int    g_pidx[NB * NSRC];  // original within-batch index

__device__ __forceinline__ int cellcoord(float v) {
    int c = (int)floorf((v + LB) * INVH);
    return min(G - 1, max(0, c));
}

// distance from p to cell slab [lo,hi] along one axis; boundary cells are
// unbounded outward (clamped points live there)
__device__ __forceinline__ float axdist(float p, int i) {
    float lo = (i == 0)     ? -1e30f : __fmaf_rn((float)i, GH, -LB);
    float hi = (i == G - 1) ?  1e30f : __fmaf_rn((float)(i + 1), GH, -LB);
    return fmaxf(0.0f, fmaxf(lo - p, p - hi));
}

__global__ void k_zero() {
    int i = blockIdx.x * blockDim.x + threadIdx.x;
    if (i < NB * NCELL) g_cnt[i] = 0;
}

__global__ void k_count(const float* __restrict__ src) {
    int i = blockIdx.x * blockDim.x + threadIdx.x;
    if (i >= NB * NSRC) return;
    int b = i / NSRC;
    float x = src[3 * i], y = src[3 * i + 1], z = src[3 * i + 2];
    int cell = (cellcoord(z) * G + cellcoord(y)) * G + cellcoord(x);
    atomicAdd(&g_cnt[b * NCELL + cell], 1);
}

#define CPT (NCELL / 1024)
__global__ void k_scan() {
    __shared__ int sm[1024];
    int b = blockIdx.x, t = threadIdx.x;
    const int* cnt = g_cnt + b * NCELL;
    int* start = g_start + b * (NCELL + 1);
    int* cur   = g_cur + b * NCELL;
    int s = 0;
    #pragma unroll
    for (int c = 0; c < CPT; c++) s += cnt[t * CPT + c];
    sm[t] = s; __syncthreads();
    for (int off = 1; off < 1024; off <<= 1) {
        int v = (t >= off) ? sm[t - off] : 0;
        __syncthreads();
        sm[t] += v;
        __syncthreads();
    }
    int run = sm[t] - s;
    #pragma unroll
    for (int c = 0; c < CPT; c++) {
        int id = t * CPT + c;
        start[id] = run; cur[id] = run;
        run += cnt[id];
    }
    if (t == 1023) start[NCELL] = NSRC;
}

__global__ void k_scatter(const float* __restrict__ src) {
    int i = blockIdx.x * blockDim.x + threadIdx.x;
    if (i >= NB * NSRC) return;
    int b = i / NSRC;
    float x = src[3 * i], y = src[3 * i + 1], z = src[3 * i + 2];
    int cell = (cellcoord(z) * G + cellcoord(y)) * G + cellcoord(x);
    int pos = atomicAdd(&g_cur[b * NCELL + cell], 1);
    float ss = __fadd_rn(__fadd_rn(__fmul_rn(x, x), __fmul_rn(y, y)), __fmul_rn(z, z));
    g_pts[b * NSRC + pos]  = make_float4(x, y, z, ss);
    g_pidx[b * NSRC + pos] = i - b * NSRC;
}

// One warp per target. Exact KNN: center cell first, then thr-pruned d=1
// neighbor cells, then row-pruned shells d>=2. Pruning margin strictly
// dominates all fp error, so the selected set (lex (value,index) order ==
// jax top_k tie-break) is unchanged.
__global__ __launch_bounds__(256) void k_query(const float* __restrict__ src,
                                               const float* __restrict__ tgt,
                                               float* __restrict__ out) {
    __shared__ int s_p0 [8][32];
    __shared__ int s_pre[8][32];

    const int w    = threadIdx.x >> 5;
    const int lane = threadIdx.x & 31;
    const int tg   = blockIdx.x * 8 + w;
    const int b    = tg / NTGT;

    const float px = tgt[3 * tg], py = tgt[3 * tg + 1], pz = tgt[3 * tg + 2];
    const float tt = __fadd_rn(__fadd_rn(__fmul_rn(px, px), __fmul_rn(py, py)),
                               __fmul_rn(pz, pz));

    const int cx = cellcoord(px), cy = cellcoord(py), cz = cellcoord(pz);
    float ex = fmaxf(fmaxf(-LB - px, px - LB), 0.0f);
    float ey = fmaxf(fmaxf(-LB - py, py - LB), 0.0f);
    float ez = fmaxf(fmaxf(-LB - pz, pz - LB), 0.0f);
    const float e = sqrtf(ex * ex + ey * ey + ez * ez);

    const float INF  = __int_as_float(0x7f800000);
    const int   IMAX = 0x7fffffff;
    float lv = INF; int li = IMAX;
    float thr_v = INF; int thr_i = IMAX;
    bool filled = false;

    const int*    cstart = g_start + b * (NCELL + 1);
    const float4* pts    = g_pts + b * NSRC;
    const int*    pidx   = g_pidx + b * NSRC;

    const int dmax = max(max(max(cx, G - 1 - cx), max(cy, G - 1 - cy)),
                         max(cz, G - 1 - cz));

    // ascending-lex bitonic sort of one (value,index) per lane
    auto sort32 = [&](float& v, int& ix) {
        #pragma unroll
        for (int kk = 2; kk <= 32; kk <<= 1) {
            #pragma unroll
            for (int j = kk >> 1; j > 0; j >>= 1) {
                const float ov = __shfl_xor_sync(FULLM, v, j);
                const int   oi = __shfl_xor_sync(FULLM, ix, j);
                const bool dirAsc = ((lane & kk) == 0);
                const bool otherLess = (ov < v) || (ov == v && oi < ix);
                const bool lower = (lane & j) == 0;
                const bool keepOther = lower ? (dirAsc ? otherLess : !otherLess)
                                             : (dirAsc ? !otherLess : otherLess);
                if (keepOther) { v = ov; ix = oi; }
            }
        }
    };

    // consume one warp-batch (hybrid serial / batch-merge), lex order
    auto consume = [&](float sqv, int jj) {
        if (filled) {
            const bool acc = (sqv < thr_v) || (sqv == thr_v && jj < thr_i);
            unsigned ball = __ballot_sync(FULLM, acc);
            const int nacc = __popc(ball);
            if (nacc == 0) return;
            if (nacc < 8) {
                do {
                    const int   sl = __ffs(ball) - 1;
                    ball &= ball - 1;
                    const float nv = __shfl_sync(FULLM, sqv, sl);
                    const int   nj = __shfl_sync(FULLM, jj,  sl);
                    const unsigned le =
                        __ballot_sync(FULLM, (lv < nv) || (lv == nv && li < nj));
                    const int ppos = __popc(le);
                    if (ppos < 32) {
                        const float pv = __shfl_up_sync(FULLM, lv, 1);
                        const int   pj = __shfl_up_sync(FULLM, li, 1);
                        if (lane > ppos)       { lv = pv; li = pj; }
                        else if (lane == ppos) { lv = nv; li = nj; }
                    }
                } while (ball);
                thr_v = __shfl_sync(FULLM, lv, 31);
                thr_i = __shfl_sync(FULLM, li, 31);
                return;
            }
            if (!acc) { sqv = INF; jj = IMAX; }
            sort32(sqv, jj);
            const float bv = __shfl_sync(FULLM, sqv, 31 - lane);
            const int   bi = __shfl_sync(FULLM, jj,  31 - lane);
            const bool keepB = (bv < lv) || (bv == lv && bi < li);
            float cv = keepB ? bv : lv;
            int   ci = keepB ? bi : li;
            #pragma unroll
            for (int j = 16; j; j >>= 1) {
                const float ov = __shfl_xor_sync(FULLM, cv, j);
                const int   oi = __shfl_xor_sync(FULLM, ci, j);
                const bool otherLess = (ov < cv) || (ov == cv && oi < ci);
                const bool lower = (lane & j) == 0;
                if (lower ? otherLess : !otherLess) { cv = ov; ci = oi; }
            }
            lv = cv; li = ci;
            thr_v = __shfl_sync(FULLM, lv, 31);
            thr_i = __shfl_sync(FULLM, li, 31);
        } else {
            sort32(sqv, jj);
            lv = sqv; li = jj;
            thr_v = __shfl_sync(FULLM, lv, 31);
            thr_i = __shfl_sync(FULLM, li, 31);
            filled = true;
        }
    };

    auto evalP = [&](int ii, float& sqv, int& jj) {
        const float4 S = pts[ii];
        jj = pidx[ii];
        float dot = __fmaf_rn(pz, S.z, __fmaf_rn(py, S.y, __fmul_rn(px, S.x)));
        sqv = __fadd_rn(__fsub_rn(tt, __fmul_rn(2.0f, dot)), S.w);
    };

    // ---- d=0: center cell, contiguous (no search) ----
    {
        const int cell = (cz * G + cy) * G + cx;
        const int p0c = cstart[cell], p1c = cstart[cell + 1];
        for (int base = p0c; base < p1c; base += 32) {
            const int ii = base + lane;
            float sqv = INF; int jj = IMAX;
            if (ii < p1c) evalP(ii, sqv, jj);
            consume(sqv, jj);
        }
    }

    // ---- d=1: 26 neighbor cells, thr-pruned by box distance ----
    {
        int p0 = 0, len = 0;
        if (lane < 26) {
            const int k26 = lane + (lane >= 13);   // skip center (13)
            const int dx = k26 % 3 - 1;
            const int dy = (k26 / 3) % 3 - 1;
            const int dz = k26 / 9 - 1;
            const int xc = cx + dx, yc = cy + dy, zc = cz + dz;
            if (xc >= 0 && xc < G && yc >= 0 && yc < G && zc >= 0 && zc < G) {
                const float dmx = axdist(px, xc);
                const float dmy = axdist(py, yc);
                const float dmz = axdist(pz, zc);
                const float sq_lb = dmx * dmx + dmy * dmy + dmz * dmz;
                // conservative: margin >> all fp error; ties can't be lost
                if (!(sq_lb * 0.999f - 1e-4f > thr_v)) {
                    const int cell = (zc * G + yc) * G + xc;
                    p0  = cstart[cell];
                    len = cstart[cell + 1] - p0;
                }
            }
        }
        int pre = len;
        #pragma unroll
        for (int off = 1; off < 32; off <<= 1) {
            int n = __shfl_up_sync(FULLM, pre, off);
            if (lane >= off) pre += n;
        }
        const int total = __shfl_sync(FULLM, pre, 31);
        pre -= len;
        s_p0 [w][lane] = p0;
        s_pre[w][lane] = pre;
        __syncwarp(FULLM);

        for (int base = 0; base < total; base += 32) {
            const int pos = base + lane;
            float sqv = INF; int jj = IMAX;
            if (pos < total) {
                int lo = 0;
                #pragma unroll
                for (int step = 16; step; step >>= 1) {
                    const int cand = lo + step;
                    if (cand < 32 && s_pre[w][cand] <= pos) lo = cand;
                }
                evalP(s_p0[w][lo] + (pos - s_pre[w][lo]), sqv, jj);
            }
            consume(sqv, jj);
        }
    }

    // ---- shells d >= 2 (rare), row-pruned ----
    for (int d = 1;;) {
        const float dm = __fmaf_rn((float)d, GH, -e);
        if (dm > 0.0f && thr_v < dm * dm) break;   // strict: protects index ties
        if (d >= dmax) break;
        ++d;
        const int nseg = 8 * d + 2 * (2 * d - 1) * (2 * d - 1);
        for (int bk = 0; bk < nseg; bk += 32) {
            const int k = bk + lane;
            bool valid = (k < nseg);
            int zc = cz, yc = cy, x0 = cx, x1 = cx;
            bool inner = false;
            if (valid) {
                if (k < 8 * d) {                  // perimeter rows (full span)
                    const int side = k / (2 * d), off = k % (2 * d);
                    int zo, yo;
                    if      (side == 0) { zo = -d; yo = -d + off; }
                    else if (side == 1) { yo =  d; zo = -d + off; }
                    else if (side == 2) { zo =  d; yo =  d - off; }
                    else                { yo = -d; zo =  d - off; }
                    zc = cz + zo; yc = cy + yo;
                    x0 = max(cx - d, 0); x1 = min(cx + d, G - 1);
                } else {                           // inner rows: 2 single cells
                    const int k2 = k - 8 * d;
                    const int w2 = 2 * d - 1;
                    const int r = k2 >> 1, side2 = k2 & 1;
                    zc = cz + (-d + 1 + r / w2);
                    yc = cy + (-d + 1 + r % w2);
                    const int x = side2 ? (cx + d) : (cx - d);
                    x0 = x1 = x;
                    inner = true;
                    if (x < 0 || x >= G) valid = false;
                }
                if (zc < 0 || zc >= G || yc < 0 || yc >= G) valid = false;
            }
            if (valid) {
                // row-level prune: y/z slab distance (+x for single cells)
                const float dmy = axdist(py, yc);
                const float dmz = axdist(pz, zc);
                float sq_lb = dmy * dmy + dmz * dmz;
                if (inner) {
                    const float dmx = axdist(px, x0);
                    sq_lb += dmx * dmx;
                }
                if (sq_lb * 0.999f - 1e-4f > thr_v) valid = false;
            }
            int p0 = 0, len = 0;
            if (valid) {
                const int cb = (zc * G + yc) * G;
                p0  = cstart[cb + x0];
                len = cstart[cb + x1 + 1] - p0;
            }
            int pre = len;
            #pragma unroll
            for (int off = 1; off < 32; off <<= 1) {
                int n = __shfl_up_sync(FULLM, pre, off);
                if (lane >= off) pre += n;
            }
            const int total = __shfl_sync(FULLM, pre, 31);
            pre -= len;
            s_p0 [w][lane] = p0;
            s_pre[w][lane] = pre;
            __syncwarp(FULLM);
            if (total == 0) continue;

            for (int base = 0; base < total; base += 32) {
                const int pos = base + lane;
                float sqv = INF; int jj = IMAX;
                if (pos < total) {
                    int lo = 0;
                    #pragma unroll
                    for (int step = 16; step; step >>= 1) {
                        const int cand = lo + step;
                        if (cand < 32 && s_pre[w][cand] <= pos) lo = cand;
                    }
                    evalP(s_p0[w][lo] + (pos - s_pre[w][lo]), sqv, jj);
                }
                consume(sqv, jj);
            }
        }
    }

    // ---- outputs ----
    const float rad  = 0.2f;
    const float rad2 = __fmul_rn(rad, rad);
    const bool  mask = (rad2 >= lv);

    float gx = 0.0f, gy = 0.0f, gz = 0.0f;
    if (mask) {
        const float* sp = src + (size_t)(b * NSRC + li) * 3;
        gx = __fdiv_rn(sp[0], rad);
        gy = __fdiv_rn(sp[1], rad);
        gz = __fdiv_rn(sp[2], rad);
    }
    const float tdx = __fdiv_rn(px, rad);
    const float tdy = __fdiv_rn(py, rad);
    const float tdz = __fdiv_rn(pz, rad);

    const size_t ee = (size_t)tg * KNN + lane;

    float* patches = out + OFF_PATCH;
    patches[3 * ee + 0] = __fsub_rn(gx, tdx);
    patches[3 * ee + 1] = __fsub_rn(gy, tdy);
    patches[3 * ee + 2] = __fsub_rn(gz, tdz);

    float* idxf = out + OFF_IDX;
    idxf[2 * ee + 0] = (float)b;
    idxf[2 * ee + 1] = (float)(mask ? li : -1);

    float* pdist = out + OFF_DIST;
    pdist[ee] = __fdiv_rn(__fsqrt_rn(fmaxf(lv, 1e-9f)), rad);

    const unsigned mball = __ballot_sync(FULLM, mask);
    if (lane == 0) {
        float* psize = out + OFF_SIZE;
        psize[tg] = (float)__popc(mball);
    }

    if (blockIdx.x == 0 && threadIdx.x < NB) {
        float* prad = out + OFF_RAD;
        prad[threadIdx.x] = rad;
    }
}

extern "C" void kernel_launch(void* const* d_in, const int* in_sizes, int n_in,
                              void* d_out, int out_size) {
    const float* src = (const float*)d_in[0];
    const float* tgt = (const float*)d_in[1];
    if (n_in >= 2 && in_sizes[0] == NB * NTGT * 3 && in_sizes[1] == NB * NSRC * 3) {
        src = (const float*)d_in[1];
        tgt = (const float*)d_in[0];
    }
    float* out = (float*)d_out;

    k_zero   <<<(NB * NCELL + 255) / 256, 256>>>();
    k_count  <<<(NB * NSRC + 255) / 256, 256>>>(src);
    k_scan   <<<NB, 1024>>>();
    k_scatter<<<(NB * NSRC + 255) / 256, 256>>>(src);
    k_query  <<<(NB * NTGT) / 8, 256>>>(src, tgt, out);
}

// round 14
// speedup vs baseline: 1.7017x; 1.0614x over previous
#include <cuda_runtime.h>
#include <cstdint>
#include <cstddef>

#define NB    4
#define NSRC  16384
#define NTGT  4096
#define KNN   32
#define FULLM 0xffffffffu

// spatial grid
#define G     32
#define NCELL (G*G*G)
#define LB    6.0f
#define GH    0.375f
#define INVH  (1.0f/GH)

// Output layout (flattened concat, all float32):
#define OFF_PATCH 0
#define OFF_IDX   1572864
#define OFF_SIZE  2621440
#define OFF_RAD   2637824
#define OFF_DIST  2637828

// __device__ scratch (no allocations allowed). Zero-initialized at load;
// g_cnt is re-zeroed by k_query's epilogue each iteration (g_cur/g_start are
// fully overwritten by k_scan, so they need no reset).
__device__ int    g_cnt[NB * NCELL];
__device__ int    g_cur[NB * NCELL];
__device__ int    g_start[NB * (NCELL + 1)];
__device__ float4 g_pts[NB * NSRC];   // (x, y, z, sumsq), cell-sorted
__device__ int    g_pidx[NB * NSRC];  // original within-batch index

__device__ __forceinline__ int cellcoord(float v) {
    int c = (int)floorf((v + LB) * INVH);
    return min(G - 1, max(0, c));
}

// distance from p to cell slab [lo,hi] along one axis; boundary cells are
// unbounded outward (clamped points live there)
__device__ __forceinline__ float axdist(float p, int i) {
    float lo = (i == 0)     ? -1e30f : __fmaf_rn((float)i, GH, -LB);
    float hi = (i == G - 1) ?  1e30f : __fmaf_rn((float)(i + 1), GH, -LB);
    return fmaxf(0.0f, fmaxf(lo - p, p - hi));
}

__global__ void k_count(const float* __restrict__ src) {
    int i = blockIdx.x * blockDim.x + threadIdx.x;
    if (i >= NB * NSRC) return;
    int b = i / NSRC;
    float x = src[3 * i], y = src[3 * i + 1], z = src[3 * i + 2];
    int cell = (cellcoord(z) * G + cellcoord(y)) * G + cellcoord(x);
    atomicAdd(&g_cnt[b * NCELL + cell], 1);
}

#define CPT (NCELL / 1024)
__global__ void k_scan() {
    __shared__ int sm[1024];
    int b = blockIdx.x, t = threadIdx.x;
    const int* cnt = g_cnt + b * NCELL;
    int* start = g_start + b * (NCELL + 1);
    int* cur   = g_cur + b * NCELL;
    int s = 0;
    #pragma unroll
    for (int c = 0; c < CPT; c++) s += cnt[t * CPT + c];
    sm[t] = s; __syncthreads();
    for (int off = 1; off < 1024; off <<= 1) {
        int v = (t >= off) ? sm[t - off] : 0;
        __syncthreads();
        sm[t] += v;
        __syncthreads();
    }
    int run = sm[t] - s;
    #pragma unroll
    for (int c = 0; c < CPT; c++) {
        int id = t * CPT + c;
        start[id] = run; cur[id] = run;
        run += cnt[id];
    }
    if (t == 1023) start[NCELL] = NSRC;
}

__global__ void k_scatter(const float* __restrict__ src) {
    int i = blockIdx.x * blockDim.x + threadIdx.x;
    if (i >= NB * NSRC) return;
    int b = i / NSRC;
    float x = src[3 * i], y = src[3 * i + 1], z = src[3 * i + 2];
    int cell = (cellcoord(z) * G + cellcoord(y)) * G + cellcoord(x);
    int pos = atomicAdd(&g_cur[b * NCELL + cell], 1);
    float ss = __fadd_rn(__fadd_rn(__fmul_rn(x, x), __fmul_rn(y, y)), __fmul_rn(z, z));
    g_pts[b * NSRC + pos]  = make_float4(x, y, z, ss);
    g_pidx[b * NSRC + pos] = i - b * NSRC;
}

// One warp per target. Exact KNN: center cell first, then thr-pruned d=1
// neighbor cells, then row-pruned shells d>=2. Pruning margin strictly
// dominates all fp error, so the selected set (lex (value,index) order ==
// jax top_k tie-break) is unchanged.
__global__ __launch_bounds__(256) void k_query(const float* __restrict__ src,
                                               const float* __restrict__ tgt,
                                               float* __restrict__ out) {
    __shared__ int s_p0 [8][32];
    __shared__ int s_pre[8][32];

    const int w    = threadIdx.x >> 5;
    const int lane = threadIdx.x & 31;
    const int tg   = blockIdx.x * 8 + w;
    const int b    = tg / NTGT;

    const float px = tgt[3 * tg], py = tgt[3 * tg + 1], pz = tgt[3 * tg + 2];
    const float tt = __fadd_rn(__fadd_rn(__fmul_rn(px, px), __fmul_rn(py, py)),
                               __fmul_rn(pz, pz));

    const int cx = cellcoord(px), cy = cellcoord(py), cz = cellcoord(pz);
    float ex = fmaxf(fmaxf(-LB - px, px - LB), 0.0f);
    float ey = fmaxf(fmaxf(-LB - py, py - LB), 0.0f);
    float ez = fmaxf(fmaxf(-LB - pz, pz - LB), 0.0f);
    const float e = sqrtf(ex * ex + ey * ey + ez * ez);

    const float INF  = __int_as_float(0x7f800000);
    const int   IMAX = 0x7fffffff;
    float lv = INF; int li = IMAX;
    float thr_v = INF; int thr_i = IMAX;
    bool filled = false;

    const int*    cstart = g_start + b * (NCELL + 1);
    const float4* pts    = g_pts + b * NSRC;
    const int*    pidx   = g_pidx + b * NSRC;

    const int dmax = max(max(max(cx, G - 1 - cx), max(cy, G - 1 - cy)),
                         max(cz, G - 1 - cz));

    // ascending-lex bitonic sort of one (value,index) per lane
    auto sort32 = [&](float& v, int& ix) {
        #pragma unroll
        for (int kk = 2; kk <= 32; kk <<= 1) {
            #pragma unroll
            for (int j = kk >> 1; j > 0; j >>= 1) {
                const float ov = __shfl_xor_sync(FULLM, v, j);
                const int   oi = __shfl_xor_sync(FULLM, ix, j);
                const bool dirAsc = ((lane & kk) == 0);
                const bool otherLess = (ov < v) || (ov == v && oi < ix);
                const bool lower = (lane & j) == 0;
                const bool keepOther = lower ? (dirAsc ? otherLess : !otherLess)
                                             : (dirAsc ? !otherLess : otherLess);
                if (keepOther) { v = ov; ix = oi; }
            }
        }
    };

    // consume one warp-batch (hybrid serial / batch-merge), lex order
    auto consume = [&](float sqv, int jj) {
        if (filled) {
            const bool acc = (sqv < thr_v) || (sqv == thr_v && jj < thr_i);
            unsigned ball = __ballot_sync(FULLM, acc);
            const int nacc = __popc(ball);
            if (nacc == 0) return;
            if (nacc < 8) {
                do {
                    const int   sl = __ffs(ball) - 1;
                    ball &= ball - 1;
                    const float nv = __shfl_sync(FULLM, sqv, sl);
                    const int   nj = __shfl_sync(FULLM, jj,  sl);
                    const unsigned le =
                        __ballot_sync(FULLM, (lv < nv) || (lv == nv && li < nj));
                    const int ppos = __popc(le);
                    if (ppos < 32) {
                        const float pv = __shfl_up_sync(FULLM, lv, 1);
                        const int   pj = __shfl_up_sync(FULLM, li, 1);
                        if (lane > ppos)       { lv = pv; li = pj; }
                        else if (lane == ppos) { lv = nv; li = nj; }
                    }
                } while (ball);
                thr_v = __shfl_sync(FULLM, lv, 31);
                thr_i = __shfl_sync(FULLM, li, 31);
                return;
            }
            if (!acc) { sqv = INF; jj = IMAX; }
            sort32(sqv, jj);
            const float bv = __shfl_sync(FULLM, sqv, 31 - lane);
            const int   bi = __shfl_sync(FULLM, jj,  31 - lane);
            const bool keepB = (bv < lv) || (bv == lv && bi < li);
            float cv = keepB ? bv : lv;
            int   ci = keepB ? bi : li;
            #pragma unroll
            for (int j = 16; j; j >>= 1) {
                const float ov = __shfl_xor_sync(FULLM, cv, j);
                const int   oi = __shfl_xor_sync(FULLM, ci, j);
                const bool otherLess = (ov < cv) || (ov == cv && oi < ci);
                const bool lower = (lane & j) == 0;
                if (lower ? otherLess : !otherLess) { cv = ov; ci = oi; }
            }
            lv = cv; li = ci;
            thr_v = __shfl_sync(FULLM, lv, 31);
            thr_i = __shfl_sync(FULLM, li, 31);
        } else {
            sort32(sqv, jj);
            lv = sqv; li = jj;
            thr_v = __shfl_sync(FULLM, lv, 31);
            thr_i = __shfl_sync(FULLM, li, 31);
            filled = true;
        }
    };

    auto evalP = [&](int ii, float& sqv, int& jj) {
        const float4 S = pts[ii];
        jj = pidx[ii];
        float dot = __fmaf_rn(pz, S.z, __fmaf_rn(py, S.y, __fmul_rn(px, S.x)));
        sqv = __fadd_rn(__fsub_rn(tt, __fmul_rn(2.0f, dot)), S.w);
    };

    // ---- d=0: center cell, contiguous (no search) ----
    {
        const int cell = (cz * G + cy) * G + cx;
        const int p0c = cstart[cell], p1c = cstart[cell + 1];
        for (int base = p0c; base < p1c; base += 32) {
            const int ii = base + lane;
            float sqv = INF; int jj = IMAX;
            if (ii < p1c) evalP(ii, sqv, jj);
            consume(sqv, jj);
        }
    }

    // ---- d=1: 26 neighbor cells, thr-pruned by box distance ----
    {
        int p0 = 0, len = 0;
        if (lane < 26) {
            const int k26 = lane + (lane >= 13);   // skip center (13)
            const int dx = k26 % 3 - 1;
            const int dy = (k26 / 3) % 3 - 1;
            const int dz = k26 / 9 - 1;
            const int xc = cx + dx, yc = cy + dy, zc = cz + dz;
            if (xc >= 0 && xc < G && yc >= 0 && yc < G && zc >= 0 && zc < G) {
                const float dmx = axdist(px, xc);
                const float dmy = axdist(py, yc);
                const float dmz = axdist(pz, zc);
                const float sq_lb = dmx * dmx + dmy * dmy + dmz * dmz;
                // conservative: margin >> all fp error; ties can't be lost
                if (!(sq_lb * 0.999f - 1e-4f > thr_v)) {
                    const int cell = (zc * G + yc) * G + xc;
                    p0  = cstart[cell];
                    len = cstart[cell + 1] - p0;
                }
            }
        }
        int pre = len;
        #pragma unroll
        for (int off = 1; off < 32; off <<= 1) {
            int n = __shfl_up_sync(FULLM, pre, off);
            if (lane >= off) pre += n;
        }
        const int total = __shfl_sync(FULLM, pre, 31);
        pre -= len;
        s_p0 [w][lane] = p0;
        s_pre[w][lane] = pre;
        __syncwarp(FULLM);

        for (int base = 0; base < total; base += 32) {
            const int pos = base + lane;
            float sqv = INF; int jj = IMAX;
            if (pos < total) {
                int lo = 0;
                #pragma unroll
                for (int step = 16; step; step >>= 1) {
                    const int cand = lo + step;
                    if (cand < 32 && s_pre[w][cand] <= pos) lo = cand;
                }
                evalP(s_p0[w][lo] + (pos - s_pre[w][lo]), sqv, jj);
            }
            consume(sqv, jj);
        }
    }

    // ---- shells d >= 2 (rare), row-pruned ----
    for (int d = 1;;) {
        const float dm = __fmaf_rn((float)d, GH, -e);
        if (dm > 0.0f && thr_v < dm * dm) break;   // strict: protects index ties
        if (d >= dmax) break;
        ++d;
        const int nseg = 8 * d + 2 * (2 * d - 1) * (2 * d - 1);
        for (int bk = 0; bk < nseg; bk += 32) {
            const int k = bk + lane;
            bool valid = (k < nseg);
            int zc = cz, yc = cy, x0 = cx, x1 = cx;
            bool inner = false;
            if (valid) {
                if (k < 8 * d) {                  // perimeter rows (full span)
                    const int side = k / (2 * d), off = k % (2 * d);
                    int zo, yo;
                    if      (side == 0) { zo = -d; yo = -d + off; }
                    else if (side == 1) { yo =  d; zo = -d + off; }
                    else if (side == 2) { zo =  d; yo =  d - off; }
                    else                { yo = -d; zo =  d - off; }
                    zc = cz + zo; yc = cy + yo;
                    x0 = max(cx - d, 0); x1 = min(cx + d, G - 1);
                } else {                           // inner rows: 2 single cells
                    const int k2 = k - 8 * d;
                    const int w2 = 2 * d - 1;
                    const int r = k2 >> 1, side2 = k2 & 1;
                    zc = cz + (-d + 1 + r / w2);
                    yc = cy + (-d + 1 + r % w2);
                    const int x = side2 ? (cx + d) : (cx - d);
                    x0 = x1 = x;
                    inner = true;
                    if (x < 0 || x >= G) valid = false;
                }
                if (zc < 0 || zc >= G || yc < 0 || yc >= G) valid = false;
            }
            if (valid) {
                // row-level prune: y/z slab distance (+x for single cells)
                const float dmy = axdist(py, yc);
                const float dmz = axdist(pz, zc);
                float sq_lb = dmy * dmy + dmz * dmz;
                if (inner) {
                    const float dmx = axdist(px, x0);
                    sq_lb += dmx * dmx;
                }
                if (sq_lb * 0.999f - 1e-4f > thr_v) valid = false;
            }
            int p0 = 0, len = 0;
            if (valid) {
                const int cb = (zc * G + yc) * G;
                p0  = cstart[cb + x0];
                len = cstart[cb + x1 + 1] - p0;
            }
            int pre = len;
            #pragma unroll
            for (int off = 1; off < 32; off <<= 1) {
                int n = __shfl_up_sync(FULLM, pre, off);
                if (lane >= off) pre += n;
            }
            const int total = __shfl_sync(FULLM, pre, 31);
            pre -= len;
            s_p0 [w][lane] = p0;
            s_pre[w][lane] = pre;
            __syncwarp(FULLM);
            if (total == 0) continue;

            for (int base = 0; base < total; base += 32) {
                const int pos = base + lane;
                float sqv = INF; int jj = IMAX;
                if (pos < total) {
                    int lo = 0;
                    #pragma unroll
                    for (int step = 16; step; step >>= 1) {
                        const int cand = lo + step;
                        if (cand < 32 && s_pre[w][cand] <= pos) lo = cand;
                    }
                    evalP(s_p0[w][lo] + (pos - s_pre[w][lo]), sqv, jj);
                }
                consume(sqv, jj);
            }
        }
    }

    // ---- outputs ----
    const float rad  = 0.2f;
    const float rad2 = __fmul_rn(rad, rad);
    const bool  mask = (rad2 >= lv);

    float gx = 0.0f, gy = 0.0f, gz = 0.0f;
    if (mask) {
        const float* sp = src + (size_t)(b * NSRC + li) * 3;
        gx = __fdiv_rn(sp[0], rad);
        gy = __fdiv_rn(sp[1], rad);
        gz = __fdiv_rn(sp[2], rad);
    }
    const float tdx = __fdiv_rn(px, rad);
    const float tdy = __fdiv_rn(py, rad);
    const float tdz = __fdiv_rn(pz, rad);

    const size_t ee = (size_t)tg * KNN + lane;

    float* patches = out + OFF_PATCH;
    patches[3 * ee + 0] = __fsub_rn(gx, tdx);
    patches[3 * ee + 1] = __fsub_rn(gy, tdy);
    patches[3 * ee + 2] = __fsub_rn(gz, tdz);

    float* idxf = out + OFF_IDX;
    idxf[2 * ee + 0] = (float)b;
    idxf[2 * ee + 1] = (float)(mask ? li : -1);

    float* pdist = out + OFF_DIST;
    pdist[ee] = __fdiv_rn(__fsqrt_rn(fmaxf(lv, 1e-9f)), rad);

    const unsigned mball = __ballot_sync(FULLM, mask);
    if (lane == 0) {
        float* psize = out + OFF_SIZE;
        psize[tg] = (float)__popc(mball);
    }

    if (blockIdx.x == 0 && threadIdx.x < NB) {
        float* prad = out + OFF_RAD;
        prad[threadIdx.x] = rad;
    }

    // ---- epilogue: reset g_cnt for the next launch (replaces k_zero) ----
    const int zi = blockIdx.x * 256 + threadIdx.x;
    if (zi < NB * NCELL) g_cnt[zi] = 0;
}

extern "C" void kernel_launch(void* const* d_in, const int* in_sizes, int n_in,
                              void* d_out, int out_size) {
    const float* src = (const float*)d_in[0];
    const float* tgt = (const float*)d_in[1];
    if (n_in >= 2 && in_sizes[0] == NB * NTGT * 3 && in_sizes[1] == NB * NSRC * 3) {
        src = (const float*)d_in[1];
        tgt = (const float*)d_in[0];
    }
    float* out = (float*)d_out;

    k_count  <<<(NB * NSRC + 255) / 256, 256>>>(src);
    k_scan   <<<NB, 1024>>>();
    k_scatter<<<(NB * NSRC + 255) / 256, 256>>>(src);
    k_query  <<<(NB * NTGT) / 8, 256>>>(src, tgt, out);
}

// round 15
// speedup vs baseline: 1.9915x; 1.1703x over previous
#include <cuda_runtime.h>
#include <cstdint>
#include <cstddef>

#define NB    4
#define NSRC  16384
#define NTGT  4096
#define KNN   32
#define FULLM 0xffffffffu

// spatial grid
#define G     32
#define NCELL (G*G*G)
#define LB    6.0f
#define GH    0.375f
#define INVH  (1.0f/GH)

// fused build: smem histogram (NCELL ints) + block-scan workspace
#define BTH        1024
#define PPT        (NSRC / BTH)     // 16 points per thread
#define CPTW       (NCELL / BTH)    // 32 cells per thread
#define SMEM_BUILD ((NCELL + BTH) * (int)sizeof(int))

// Output layout (flattened concat, all float32):
#define OFF_PATCH 0
#define OFF_IDX   1572864
#define OFF_SIZE  2621440
#define OFF_RAD   2637824
#define OFF_DIST  2637828

// __device__ scratch (no allocations allowed)
__device__ int    g_start[NB * (NCELL + 1)];
__device__ float4 g_pts[NB * NSRC];   // (x, y, z, sumsq), cell-sorted
__device__ int    g_pidx[NB * NSRC];  // original within-batch index

__device__ __forceinline__ int cellcoord(float v) {
    int c = (int)floorf((v + LB) * INVH);
    return min(G - 1, max(0, c));
}

// distance from p to cell slab along one axis; boundary cells unbounded outward
__device__ __forceinline__ float axdist(float p, int i) {
    float lo = (i == 0)     ? -1e30f : __fmaf_rn((float)i, GH, -LB);
    float hi = (i == G - 1) ?  1e30f : __fmaf_rn((float)(i + 1), GH, -LB);
    return fmaxf(0.0f, fmaxf(lo - p, p - hi));
}

// ONE kernel: histogram + scan + scatter, all in shared memory.
// Block b handles batch b (grid = NB).
__global__ __launch_bounds__(BTH) void k_build(const float* __restrict__ src) {
    extern __shared__ int smem[];
    int* scnt = smem;            // NCELL: counts -> start-cursors
    int* ssum = smem + NCELL;    // BTH: block scan workspace

    const int b = blockIdx.x;
    const int t = threadIdx.x;
    const float* sb = src + (size_t)b * NSRC * 3;

    // 1) zero histogram
    #pragma unroll
    for (int c = 0; c < CPTW; c++) scnt[t + c * BTH] = 0;
    __syncthreads();

    // 2) count (warp-coalesced point assignment: il = t + k*BTH)
    #pragma unroll
    for (int k = 0; k < PPT; k++) {
        const int il = t + k * BTH;
        const float x = sb[3 * il], y = sb[3 * il + 1], z = sb[3 * il + 2];
        const int cell = (cellcoord(z) * G + cellcoord(y)) * G + cellcoord(x);
        atomicAdd(&scnt[cell], 1);
    }
    __syncthreads();

    // 3) scan: thread t owns cells [t*CPTW, (t+1)*CPTW)
    int cnt[CPTW];
    int s = 0;
    #pragma unroll
    for (int c = 0; c < CPTW; c++) { cnt[c] = scnt[t * CPTW + c]; s += cnt[c]; }
    ssum[t] = s;
    __syncthreads();
    for (int off = 1; off < BTH; off <<= 1) {
        int v = (t >= off) ? ssum[t - off] : 0;
        __syncthreads();
        ssum[t] += v;
        __syncthreads();
    }
    int run = ssum[t] - s;       // exclusive prefix of this thread's chunk
    int* gstart = g_start + b * (NCELL + 1);
    #pragma unroll
    for (int c = 0; c < CPTW; c++) {
        const int id = t * CPTW + c;
        gstart[id]  = run;
        scnt[id]    = run;       // becomes the scatter cursor
        run += cnt[c];
    }
    if (t == BTH - 1) gstart[NCELL] = NSRC;
    __syncthreads();

    // 4) scatter
    #pragma unroll
    for (int k = 0; k < PPT; k++) {
        const int il = t + k * BTH;
        const float x = sb[3 * il], y = sb[3 * il + 1], z = sb[3 * il + 2];
        const int cell = (cellcoord(z) * G + cellcoord(y)) * G + cellcoord(x);
        const int pos = atomicAdd(&scnt[cell], 1);
        const float ss = __fadd_rn(__fadd_rn(__fmul_rn(x, x), __fmul_rn(y, y)),
                                   __fmul_rn(z, z));
        g_pts [b * NSRC + pos] = make_float4(x, y, z, ss);
        g_pidx[b * NSRC + pos] = il;
    }
}

// One warp per target. Exact KNN: center cell first, then thr-pruned d=1
// neighbor cells, then row-pruned shells d>=2. Pruning margin strictly
// dominates all fp error; lex (value,index) order == jax top_k tie-break,
// scan-order invariant (so smem-atomic scatter order is irrelevant).
__global__ __launch_bounds__(256) void k_query(const float* __restrict__ src,
                                               const float* __restrict__ tgt,
                                               float* __restrict__ out) {
    __shared__ int s_p0 [8][32];
    __shared__ int s_pre[8][32];

    const int w    = threadIdx.x >> 5;
    const int lane = threadIdx.x & 31;
    const int tg   = blockIdx.x * 8 + w;
    const int b    = tg / NTGT;

    const float px = tgt[3 * tg], py = tgt[3 * tg + 1], pz = tgt[3 * tg + 2];
    const float tt = __fadd_rn(__fadd_rn(__fmul_rn(px, px), __fmul_rn(py, py)),
                               __fmul_rn(pz, pz));

    const int cx = cellcoord(px), cy = cellcoord(py), cz = cellcoord(pz);
    float ex = fmaxf(fmaxf(-LB - px, px - LB), 0.0f);
    float ey = fmaxf(fmaxf(-LB - py, py - LB), 0.0f);
    float ez = fmaxf(fmaxf(-LB - pz, pz - LB), 0.0f);
    const float e = sqrtf(ex * ex + ey * ey + ez * ez);

    const float INF  = __int_as_float(0x7f800000);
    const int   IMAX = 0x7fffffff;
    float lv = INF; int li = IMAX;
    float thr_v = INF; int thr_i = IMAX;
    bool filled = false;

    const int*    cstart = g_start + b * (NCELL + 1);
    const float4* pts    = g_pts + b * NSRC;
    const int*    pidx   = g_pidx + b * NSRC;

    const int dmax = max(max(max(cx, G - 1 - cx), max(cy, G - 1 - cy)),
                         max(cz, G - 1 - cz));

    // ascending-lex bitonic sort of one (value,index) per lane
    auto sort32 = [&](float& v, int& ix) {
        #pragma unroll
        for (int kk = 2; kk <= 32; kk <<= 1) {
            #pragma unroll
            for (int j = kk >> 1; j > 0; j >>= 1) {
                const float ov = __shfl_xor_sync(FULLM, v, j);
                const int   oi = __shfl_xor_sync(FULLM, ix, j);
                const bool dirAsc = ((lane & kk) == 0);
                const bool otherLess = (ov < v) || (ov == v && oi < ix);
                const bool lower = (lane & j) == 0;
                const bool keepOther = lower ? (dirAsc ? otherLess : !otherLess)
                                             : (dirAsc ? !otherLess : otherLess);
                if (keepOther) { v = ov; ix = oi; }
            }
        }
    };

    // consume one warp-batch (hybrid serial / batch-merge), lex order
    auto consume = [&](float sqv, int jj) {
        if (filled) {
            const bool acc = (sqv < thr_v) || (sqv == thr_v && jj < thr_i);
            unsigned ball = __ballot_sync(FULLM, acc);
            const int nacc = __popc(ball);
            if (nacc == 0) return;
            if (nacc < 8) {
                do {
                    const int   sl = __ffs(ball) - 1;
                    ball &= ball - 1;
                    const float nv = __shfl_sync(FULLM, sqv, sl);
                    const int   nj = __shfl_sync(FULLM, jj,  sl);
                    const unsigned le =
                        __ballot_sync(FULLM, (lv < nv) || (lv == nv && li < nj));
                    const int ppos = __popc(le);
                    if (ppos < 32) {
                        const float pv = __shfl_up_sync(FULLM, lv, 1);
                        const int   pj = __shfl_up_sync(FULLM, li, 1);
                        if (lane > ppos)       { lv = pv; li = pj; }
                        else if (lane == ppos) { lv = nv; li = nj; }
                    }
                } while (ball);
                thr_v = __shfl_sync(FULLM, lv, 31);
                thr_i = __shfl_sync(FULLM, li, 31);
                return;
            }
            if (!acc) { sqv = INF; jj = IMAX; }
            sort32(sqv, jj);
            const float bv = __shfl_sync(FULLM, sqv, 31 - lane);
            const int   bi = __shfl_sync(FULLM, jj,  31 - lane);
            const bool keepB = (bv < lv) || (bv == lv && bi < li);
            float cv = keepB ? bv : lv;
            int   ci = keepB ? bi : li;
            #pragma unroll
            for (int j = 16; j; j >>= 1) {
                const float ov = __shfl_xor_sync(FULLM, cv, j);
                const int   oi = __shfl_xor_sync(FULLM, ci, j);
                const bool otherLess = (ov < cv) || (ov == cv && oi < ci);
                const bool lower = (lane & j) == 0;
                if (lower ? otherLess : !otherLess) { cv = ov; ci = oi; }
            }
            lv = cv; li = ci;
            thr_v = __shfl_sync(FULLM, lv, 31);
            thr_i = __shfl_sync(FULLM, li, 31);
        } else {
            sort32(sqv, jj);
            lv = sqv; li = jj;
            thr_v = __shfl_sync(FULLM, lv, 31);
            thr_i = __shfl_sync(FULLM, li, 31);
            filled = true;
        }
    };

    auto evalP = [&](int ii, float& sqv, int& jj) {
        const float4 S = pts[ii];
        jj = pidx[ii];
        float dot = __fmaf_rn(pz, S.z, __fmaf_rn(py, S.y, __fmul_rn(px, S.x)));
        sqv = __fadd_rn(__fsub_rn(tt, __fmul_rn(2.0f, dot)), S.w);
    };

    // ---- d=0: center cell, contiguous (no search) ----
    {
        const int cell = (cz * G + cy) * G + cx;
        const int p0c = cstart[cell], p1c = cstart[cell + 1];
        for (int base = p0c; base < p1c; base += 32) {
            const int ii = base + lane;
            float sqv = INF; int jj = IMAX;
            if (ii < p1c) evalP(ii, sqv, jj);
            consume(sqv, jj);
        }
    }

    // ---- d=1: 26 neighbor cells, thr-pruned by box distance ----
    {
        int p0 = 0, len = 0;
        if (lane < 26) {
            const int k26 = lane + (lane >= 13);   // skip center (13)
            const int dx = k26 % 3 - 1;
            const int dy = (k26 / 3) % 3 - 1;
            const int dz = k26 / 9 - 1;
            const int xc = cx + dx, yc = cy + dy, zc = cz + dz;
            if (xc >= 0 && xc < G && yc >= 0 && yc < G && zc >= 0 && zc < G) {
                const float dmx = axdist(px, xc);
                const float dmy = axdist(py, yc);
                const float dmz = axdist(pz, zc);
                const float sq_lb = dmx * dmx + dmy * dmy + dmz * dmz;
                // conservative: margin >> all fp error; ties can't be lost
                if (!(sq_lb * 0.999f - 1e-4f > thr_v)) {
                    const int cell = (zc * G + yc) * G + xc;
                    p0  = cstart[cell];
                    len = cstart[cell + 1] - p0;
                }
            }
        }
        int pre = len;
        #pragma unroll
        for (int off = 1; off < 32; off <<= 1) {
            int n = __shfl_up_sync(FULLM, pre, off);
            if (lane >= off) pre += n;
        }
        const int total = __shfl_sync(FULLM, pre, 31);
        pre -= len;
        s_p0 [w][lane] = p0;
        s_pre[w][lane] = pre;
        __syncwarp(FULLM);

        for (int base = 0; base < total; base += 32) {
            const int pos = base + lane;
            float sqv = INF; int jj = IMAX;
            if (pos < total) {
                int lo = 0;
                #pragma unroll
                for (int step = 16; step; step >>= 1) {
                    const int cand = lo + step;
                    if (cand < 32 && s_pre[w][cand] <= pos) lo = cand;
                }
                evalP(s_p0[w][lo] + (pos - s_pre[w][lo]), sqv, jj);
            }
            consume(sqv, jj);
        }
    }

    // ---- shells d >= 2 (rare), row-pruned ----
    for (int d = 1;;) {
        const float dm = __fmaf_rn((float)d, GH, -e);
        if (dm > 0.0f && thr_v < dm * dm) break;   // strict: protects index ties
        if (d >= dmax) break;
        ++d;
        const int nseg = 8 * d + 2 * (2 * d - 1) * (2 * d - 1);
        for (int bk = 0; bk < nseg; bk += 32) {
            const int k = bk + lane;
            bool valid = (k < nseg);
            int zc = cz, yc = cy, x0 = cx, x1 = cx;
            bool inner = false;
            if (valid) {
                if (k < 8 * d) {                  // perimeter rows (full span)
                    const int side = k / (2 * d), off = k % (2 * d);
                    int zo, yo;
                    if      (side == 0) { zo = -d; yo = -d + off; }
                    else if (side == 1) { yo =  d; zo = -d + off; }
                    else if (side == 2) { zo =  d; yo =  d - off; }
                    else                { yo = -d; zo =  d - off; }
                    zc = cz + zo; yc = cy + yo;
                    x0 = max(cx - d, 0); x1 = min(cx + d, G - 1);
                } else {                           // inner rows: 2 single cells
                    const int k2 = k - 8 * d;
                    const int w2 = 2 * d - 1;
                    const int r = k2 >> 1, side2 = k2 & 1;
                    zc = cz + (-d + 1 + r / w2);
                    yc = cy + (-d + 1 + r % w2);
                    const int x = side2 ? (cx + d) : (cx - d);
                    x0 = x1 = x;
                    inner = true;
                    if (x < 0 || x >= G) valid = false;
                }
                if (zc < 0 || zc >= G || yc < 0 || yc >= G) valid = false;
            }
            if (valid) {
                const float dmy = axdist(py, yc);
                const float dmz = axdist(pz, zc);
                float sq_lb = dmy * dmy + dmz * dmz;
                if (inner) {
                    const float dmx = axdist(px, x0);
                    sq_lb += dmx * dmx;
                }
                if (sq_lb * 0.999f - 1e-4f > thr_v) valid = false;
            }
            int p0 = 0, len = 0;
            if (valid) {
                const int cb = (zc * G + yc) * G;
                p0  = cstart[cb + x0];
                len = cstart[cb + x1 + 1] - p0;
            }
            int pre = len;
            #pragma unroll
            for (int off = 1; off < 32; off <<= 1) {
                int n = __shfl_up_sync(FULLM, pre, off);
                if (lane >= off) pre += n;
            }
            const int total = __shfl_sync(FULLM, pre, 31);
            pre -= len;
            s_p0 [w][lane] = p0;
            s_pre[w][lane] = pre;
            __syncwarp(FULLM);
            if (total == 0) continue;

            for (int base = 0; base < total; base += 32) {
                const int pos = base + lane;
                float sqv = INF; int jj = IMAX;
                if (pos < total) {
                    int lo = 0;
                    #pragma unroll
                    for (int step = 16; step; step >>= 1) {
                        const int cand = lo + step;
                        if (cand < 32 && s_pre[w][cand] <= pos) lo = cand;
                    }
                    evalP(s_p0[w][lo] + (pos - s_pre[w][lo]), sqv, jj);
                }
                consume(sqv, jj);
            }
        }
    }

    // ---- outputs ----
    const float rad  = 0.2f;
    const float rad2 = __fmul_rn(rad, rad);
    const bool  mask = (rad2 >= lv);

    float gx = 0.0f, gy = 0.0f, gz = 0.0f;
    if (mask) {
        const float* sp = src + (size_t)(b * NSRC + li) * 3;
        gx = __fdiv_rn(sp[0], rad);
        gy = __fdiv_rn(sp[1], rad);
        gz = __fdiv_rn(sp[2], rad);
    }
    const float tdx = __fdiv_rn(px, rad);
    const float tdy = __fdiv_rn(py, rad);
    const float tdz = __fdiv_rn(pz, rad);

    const size_t ee = (size_t)tg * KNN + lane;

    float* patches = out + OFF_PATCH;
    patches[3 * ee + 0] = __fsub_rn(gx, tdx);
    patches[3 * ee + 1] = __fsub_rn(gy, tdy);
    patches[3 * ee + 2] = __fsub_rn(gz, tdz);

    float* idxf = out + OFF_IDX;
    idxf[2 * ee + 0] = (float)b;
    idxf[2 * ee + 1] = (float)(mask ? li : -1);

    float* pdist = out + OFF_DIST;
    pdist[ee] = __fdiv_rn(__fsqrt_rn(fmaxf(lv, 1e-9f)), rad);

    const unsigned mball = __ballot_sync(FULLM, mask);
    if (lane == 0) {
        float* psize = out + OFF_SIZE;
        psize[tg] = (float)__popc(mball);
    }

    if (blockIdx.x == 0 && threadIdx.x < NB) {
        float* prad = out + OFF_RAD;
        prad[threadIdx.x] = rad;
    }
}

extern "C" void kernel_launch(void* const* d_in, const int* in_sizes, int n_in,
                              void* d_out, int out_size) {
    const float* src = (const float*)d_in[0];
    const float* tgt = (const float*)d_in[1];
    if (n_in >= 2 && in_sizes[0] == NB * NTGT * 3 && in_sizes[1] == NB * NSRC * 3) {
        src = (const float*)d_in[1];
        tgt = (const float*)d_in[0];
    }
    float* out = (float*)d_out;

    static bool attr_set = false;
    if (!attr_set) {
        cudaFuncSetAttribute(k_build, cudaFuncAttributeMaxDynamicSharedMemorySize,
                             SMEM_BUILD);
        attr_set = true;
    }

    k_build<<<NB, BTH, SMEM_BUILD>>>(src);
    k_query<<<(NB * NTGT) / 8, 256>>>(src, tgt, out);
}

// round 16
// speedup vs baseline: 2.0697x; 1.0393x over previous
#include <cuda_runtime.h>
#include <cstdint>
#include <cstddef>

#define NB    4
#define NSRC  16384
#define NTGT  4096
#define KNN   32
#define FULLM 0xffffffffu

// spatial grid
#define G     32
#define NCELL (G*G*G)
#define LB    6.0f
#define GH    0.375f
#define INVH  (1.0f/GH)

// fused build: PADDED smem histogram (+1 int per 32 to kill bank conflicts)
#define BTH        1024
#define PPT        (NSRC / BTH)        // 16 points per thread
#define CPTW       (NCELL / BTH)       // 32 cells per thread
#define NPAD       (NCELL + NCELL / 32)
#define PADI(i)    ((i) + ((i) >> 5))
#define SMEM_BUILD ((NPAD + BTH) * (int)sizeof(int))

// Output layout (flattened concat, all float32):
#define OFF_PATCH 0
#define OFF_IDX   1572864
#define OFF_SIZE  2621440
#define OFF_RAD   2637824
#define OFF_DIST  2637828

// __device__ scratch (no allocations allowed)
__device__ int    g_start[NB * (NCELL + 1)];
__device__ float4 g_pts[NB * NSRC];   // (x, y, z, sumsq), cell-sorted
__device__ int    g_pidx[NB * NSRC];  // original within-batch index

__device__ __forceinline__ int cellcoord(float v) {
    int c = (int)floorf((v + LB) * INVH);
    return min(G - 1, max(0, c));
}

// distance from p to cell slab along one axis; boundary cells unbounded outward
__device__ __forceinline__ float axdist(float p, int i) {
    float lo = (i == 0)     ? -1e30f : __fmaf_rn((float)i, GH, -LB);
    float hi = (i == G - 1) ?  1e30f : __fmaf_rn((float)(i + 1), GH, -LB);
    return fmaxf(0.0f, fmaxf(lo - p, p - hi));
}

// ONE kernel: histogram + scan + scatter, all in shared memory.
// Padded layout makes the chunked scan accesses conflict-free
// (lane stride 33 ints instead of 32).
__global__ __launch_bounds__(BTH) void k_build(const float* __restrict__ src) {
    extern __shared__ int smem[];
    int* scnt = smem;            // NPAD: counts -> start-cursors (padded)
    int* ssum = smem + NPAD;     // BTH: block scan workspace

    const int b = blockIdx.x;
    const int t = threadIdx.x;
    const float* sb = src + (size_t)b * NSRC * 3;

    // 1) zero padded histogram (linear, coalesced)
    for (int i = t; i < NPAD; i += BTH) scnt[i] = 0;
    __syncthreads();

    // 2) count (spread-address smem atomics)
    #pragma unroll
    for (int k = 0; k < PPT; k++) {
        const int il = t + k * BTH;
        const float x = sb[3 * il], y = sb[3 * il + 1], z = sb[3 * il + 2];
        const int cell = (cellcoord(z) * G + cellcoord(y)) * G + cellcoord(x);
        atomicAdd(&scnt[PADI(cell)], 1);
    }
    __syncthreads();

    // 3) scan: thread t owns cells [t*CPTW, (t+1)*CPTW); padded -> conflict-free
    int cnt[CPTW];
    int s = 0;
    #pragma unroll
    for (int c = 0; c < CPTW; c++) {
        cnt[c] = scnt[PADI(t * CPTW + c)];
        s += cnt[c];
    }
    ssum[t] = s;
    __syncthreads();
    for (int off = 1; off < BTH; off <<= 1) {
        int v = (t >= off) ? ssum[t - off] : 0;
        __syncthreads();
        ssum[t] += v;
        __syncthreads();
    }
    int run = ssum[t] - s;       // exclusive prefix of this thread's chunk
    int* gstart = g_start + b * (NCELL + 1);
    #pragma unroll
    for (int c = 0; c < CPTW; c++) {
        const int id = t * CPTW + c;
        gstart[id]        = run;
        scnt[PADI(id)]    = run;  // becomes the scatter cursor (conflict-free)
        run += cnt[c];
    }
    if (t == BTH - 1) gstart[NCELL] = NSRC;
    __syncthreads();

    // 4) scatter
    #pragma unroll
    for (int k = 0; k < PPT; k++) {
        const int il = t + k * BTH;
        const float x = sb[3 * il], y = sb[3 * il + 1], z = sb[3 * il + 2];
        const int cell = (cellcoord(z) * G + cellcoord(y)) * G + cellcoord(x);
        const int pos = atomicAdd(&scnt[PADI(cell)], 1);
        const float ss = __fadd_rn(__fadd_rn(__fmul_rn(x, x), __fmul_rn(y, y)),
                                   __fmul_rn(z, z));
        g_pts [b * NSRC + pos] = make_float4(x, y, z, ss);
        g_pidx[b * NSRC + pos] = il;
    }
}

// One warp per target. Exact KNN: center cell first, then thr-pruned d=1
// neighbor cells, then row-pruned shells d>=2. Pruning margin strictly
// dominates all fp error; lex (value,index) order == jax top_k tie-break,
// scan-order invariant (so smem-atomic scatter order is irrelevant).
__global__ __launch_bounds__(256) void k_query(const float* __restrict__ src,
                                               const float* __restrict__ tgt,
                                               float* __restrict__ out) {
    __shared__ int s_p0 [8][32];
    __shared__ int s_pre[8][32];

    const int w    = threadIdx.x >> 5;
    const int lane = threadIdx.x & 31;
    const int tg   = blockIdx.x * 8 + w;
    const int b    = tg / NTGT;

    const float px = tgt[3 * tg], py = tgt[3 * tg + 1], pz = tgt[3 * tg + 2];
    const float tt = __fadd_rn(__fadd_rn(__fmul_rn(px, px), __fmul_rn(py, py)),
                               __fmul_rn(pz, pz));

    const int cx = cellcoord(px), cy = cellcoord(py), cz = cellcoord(pz);
    float ex = fmaxf(fmaxf(-LB - px, px - LB), 0.0f);
    float ey = fmaxf(fmaxf(-LB - py, py - LB), 0.0f);
    float ez = fmaxf(fmaxf(-LB - pz, pz - LB), 0.0f);
    const float e = sqrtf(ex * ex + ey * ey + ez * ez);

    const float INF  = __int_as_float(0x7f800000);
    const int   IMAX = 0x7fffffff;
    float lv = INF; int li = IMAX;
    float thr_v = INF; int thr_i = IMAX;
    bool filled = false;

    const int*    cstart = g_start + b * (NCELL + 1);
    const float4* pts    = g_pts + b * NSRC;
    const int*    pidx   = g_pidx + b * NSRC;

    const int dmax = max(max(max(cx, G - 1 - cx), max(cy, G - 1 - cy)),
                         max(cz, G - 1 - cz));

    // ascending-lex bitonic sort of one (value,index) per lane
    auto sort32 = [&](float& v, int& ix) {
        #pragma unroll
        for (int kk = 2; kk <= 32; kk <<= 1) {
            #pragma unroll
            for (int j = kk >> 1; j > 0; j >>= 1) {
                const float ov = __shfl_xor_sync(FULLM, v, j);
                const int   oi = __shfl_xor_sync(FULLM, ix, j);
                const bool dirAsc = ((lane & kk) == 0);
                const bool otherLess = (ov < v) || (ov == v && oi < ix);
                const bool lower = (lane & j) == 0;
                const bool keepOther = lower ? (dirAsc ? otherLess : !otherLess)
                                             : (dirAsc ? !otherLess : otherLess);
                if (keepOther) { v = ov; ix = oi; }
            }
        }
    };

    // consume one warp-batch (hybrid serial / batch-merge), lex order
    auto consume = [&](float sqv, int jj) {
        if (filled) {
            const bool acc = (sqv < thr_v) || (sqv == thr_v && jj < thr_i);
            unsigned ball = __ballot_sync(FULLM, acc);
            const int nacc = __popc(ball);
            if (nacc == 0) return;
            if (nacc < 8) {
                do {
                    const int   sl = __ffs(ball) - 1;
                    ball &= ball - 1;
                    const float nv = __shfl_sync(FULLM, sqv, sl);
                    const int   nj = __shfl_sync(FULLM, jj,  sl);
                    const unsigned le =
                        __ballot_sync(FULLM, (lv < nv) || (lv == nv && li < nj));
                    const int ppos = __popc(le);
                    if (ppos < 32) {
                        const float pv = __shfl_up_sync(FULLM, lv, 1);
                        const int   pj = __shfl_up_sync(FULLM, li, 1);
                        if (lane > ppos)       { lv = pv; li = pj; }
                        else if (lane == ppos) { lv = nv; li = nj; }
                    }
                } while (ball);
                thr_v = __shfl_sync(FULLM, lv, 31);
                thr_i = __shfl_sync(FULLM, li, 31);
                return;
            }
            if (!acc) { sqv = INF; jj = IMAX; }
            sort32(sqv, jj);
            const float bv = __shfl_sync(FULLM, sqv, 31 - lane);
            const int   bi = __shfl_sync(FULLM, jj,  31 - lane);
            const bool keepB = (bv < lv) || (bv == lv && bi < li);
            float cv = keepB ? bv : lv;
            int   ci = keepB ? bi : li;
            #pragma unroll
            for (int j = 16; j; j >>= 1) {
                const float ov = __shfl_xor_sync(FULLM, cv, j);
                const int   oi = __shfl_xor_sync(FULLM, ci, j);
                const bool otherLess = (ov < cv) || (ov == cv && oi < ci);
                const bool lower = (lane & j) == 0;
                if (lower ? otherLess : !otherLess) { cv = ov; ci = oi; }
            }
            lv = cv; li = ci;
            thr_v = __shfl_sync(FULLM, lv, 31);
            thr_i = __shfl_sync(FULLM, li, 31);
        } else {
            sort32(sqv, jj);
            lv = sqv; li = jj;
            thr_v = __shfl_sync(FULLM, lv, 31);
            thr_i = __shfl_sync(FULLM, li, 31);
            filled = true;
        }
    };

    auto evalP = [&](int ii, float& sqv, int& jj) {
        const float4 S = pts[ii];
        jj = pidx[ii];
        float dot = __fmaf_rn(pz, S.z, __fmaf_rn(py, S.y, __fmul_rn(px, S.x)));
        sqv = __fadd_rn(__fsub_rn(tt, __fmul_rn(2.0f, dot)), S.w);
    };

    // ---- d=0: center cell, contiguous (no search) ----
    {
        const int cell = (cz * G + cy) * G + cx;
        const int p0c = cstart[cell], p1c = cstart[cell + 1];
        for (int base = p0c; base < p1c; base += 32) {
            const int ii = base + lane;
            float sqv = INF; int jj = IMAX;
            if (ii < p1c) evalP(ii, sqv, jj);
            consume(sqv, jj);
        }
    }

    // ---- d=1: 26 neighbor cells, thr-pruned by box distance ----
    {
        int p0 = 0, len = 0;
        if (lane < 26) {
            const int k26 = lane + (lane >= 13);   // skip center (13)
            const int dx = k26 % 3 - 1;
            const int dy = (k26 / 3) % 3 - 1;
            const int dz = k26 / 9 - 1;
            const int xc = cx + dx, yc = cy + dy, zc = cz + dz;
            if (xc >= 0 && xc < G && yc >= 0 && yc < G && zc >= 0 && zc < G) {
                const float dmx = axdist(px, xc);
                const float dmy = axdist(py, yc);
                const float dmz = axdist(pz, zc);
                const float sq_lb = dmx * dmx + dmy * dmy + dmz * dmz;
                // conservative: margin >> all fp error; ties can't be lost
                if (!(sq_lb * 0.999f - 1e-4f > thr_v)) {
                    const int cell = (zc * G + yc) * G + xc;
                    p0  = cstart[cell];
                    len = cstart[cell + 1] - p0;
                }
            }
        }
        int pre = len;
        #pragma unroll
        for (int off = 1; off < 32; off <<= 1) {
            int n = __shfl_up_sync(FULLM, pre, off);
            if (lane >= off) pre += n;
        }
        const int total = __shfl_sync(FULLM, pre, 31);
        pre -= len;
        s_p0 [w][lane] = p0;
        s_pre[w][lane] = pre;
        __syncwarp(FULLM);

        for (int base = 0; base < total; base += 32) {
            const int pos = base + lane;
            float sqv = INF; int jj = IMAX;
            if (pos < total) {
                int lo = 0;
                #pragma unroll
                for (int step = 16; step; step >>= 1) {
                    const int cand = lo + step;
                    if (cand < 32 && s_pre[w][cand] <= pos) lo = cand;
                }
                evalP(s_p0[w][lo] + (pos - s_pre[w][lo]), sqv, jj);
            }
            consume(sqv, jj);
        }
    }

    // ---- shells d >= 2 (rare), row-pruned ----
    for (int d = 1;;) {
        const float dm = __fmaf_rn((float)d, GH, -e);
        if (dm > 0.0f && thr_v < dm * dm) break;   // strict: protects index ties
        if (d >= dmax) break;
        ++d;
        const int nseg = 8 * d + 2 * (2 * d - 1) * (2 * d - 1);
        for (int bk = 0; bk < nseg; bk += 32) {
            const int k = bk + lane;
            bool valid = (k < nseg);
            int zc = cz, yc = cy, x0 = cx, x1 = cx;
            bool inner = false;
            if (valid) {
                if (k < 8 * d) {                  // perimeter rows (full span)
                    const int side = k / (2 * d), off = k % (2 * d);
                    int zo, yo;
                    if      (side == 0) { zo = -d; yo = -d + off; }
                    else if (side == 1) { yo =  d; zo = -d + off; }
                    else if (side == 2) { zo =  d; yo =  d - off; }
                    else                { yo = -d; zo =  d - off; }
                    zc = cz + zo; yc = cy + yo;
                    x0 = max(cx - d, 0); x1 = min(cx + d, G - 1);
                } else {                           // inner rows: 2 single cells
                    const int k2 = k - 8 * d;
                    const int w2 = 2 * d - 1;
                    const int r = k2 >> 1, side2 = k2 & 1;
                    zc = cz + (-d + 1 + r / w2);
                    yc = cy + (-d + 1 + r % w2);
                    const int x = side2 ? (cx + d) : (cx - d);
                    x0 = x1 = x;
                    inner = true;
                    if (x < 0 || x >= G) valid = false;
                }
                if (zc < 0 || zc >= G || yc < 0 || yc >= G) valid = false;
            }
            if (valid) {
                const float dmy = axdist(py, yc);
                const float dmz = axdist(pz, zc);
                float sq_lb = dmy * dmy + dmz * dmz;
                if (inner) {
                    const float dmx = axdist(px, x0);
                    sq_lb += dmx * dmx;
                }
                if (sq_lb * 0.999f - 1e-4f > thr_v) valid = false;
            }
            int p0 = 0, len = 0;
            if (valid) {
                const int cb = (zc * G + yc) * G;
                p0  = cstart[cb + x0];
                len = cstart[cb + x1 + 1] - p0;
            }
            int pre = len;
            #pragma unroll
            for (int off = 1; off < 32; off <<= 1) {
                int n = __shfl_up_sync(FULLM, pre, off);
                if (lane >= off) pre += n;
            }
            const int total = __shfl_sync(FULLM, pre, 31);
            pre -= len;
            s_p0 [w][lane] = p0;
            s_pre[w][lane] = pre;
            __syncwarp(FULLM);
            if (total == 0) continue;

            for (int base = 0; base < total; base += 32) {
                const int pos = base + lane;
                float sqv = INF; int jj = IMAX;
                if (pos < total) {
                    int lo = 0;
                    #pragma unroll
                    for (int step = 16; step; step >>= 1) {
                        const int cand = lo + step;
                        if (cand < 32 && s_pre[w][cand] <= pos) lo = cand;
                    }
                    evalP(s_p0[w][lo] + (pos - s_pre[w][lo]), sqv, jj);
                }
                consume(sqv, jj);
            }
        }
    }

    // ---- outputs ----
    const float rad  = 0.2f;
    const float rad2 = __fmul_rn(rad, rad);
    const bool  mask = (rad2 >= lv);

    float gx = 0.0f, gy = 0.0f, gz = 0.0f;
    if (mask) {
        const float* sp = src + (size_t)(b * NSRC + li) * 3;
        gx = __fdiv_rn(sp[0], rad);
        gy = __fdiv_rn(sp[1], rad);
        gz = __fdiv_rn(sp[2], rad);
    }
    const float tdx = __fdiv_rn(px, rad);
    const float tdy = __fdiv_rn(py, rad);
    const float tdz = __fdiv_rn(pz, rad);

    const size_t ee = (size_t)tg * KNN + lane;

    float* patches = out + OFF_PATCH;
    patches[3 * ee + 0] = __fsub_rn(gx, tdx);
    patches[3 * ee + 1] = __fsub_rn(gy, tdy);
    patches[3 * ee + 2] = __fsub_rn(gz, tdz);

    float* idxf = out + OFF_IDX;
    idxf[2 * ee + 0] = (float)b;
    idxf[2 * ee + 1] = (float)(mask ? li : -1);

    float* pdist = out + OFF_DIST;
    pdist[ee] = __fdiv_rn(__fsqrt_rn(fmaxf(lv, 1e-9f)), rad);

    const unsigned mball = __ballot_sync(FULLM, mask);
    if (lane == 0) {
        float* psize = out + OFF_SIZE;
        psize[tg] = (float)__popc(mball);
    }

    if (blockIdx.x == 0 && threadIdx.x < NB) {
        float* prad = out + OFF_RAD;
        prad[threadIdx.x] = rad;
    }
}

extern "C" void kernel_launch(void* const* d_in, const int* in_sizes, int n_in,
                              void* d_out, int out_size) {
    const float* src = (const float*)d_in[0];
    const float* tgt = (const float*)d_in[1];
    if (n_in >= 2 && in_sizes[0] == NB * NTGT * 3 && in_sizes[1] == NB * NSRC * 3) {
        src = (const float*)d_in[1];
        tgt = (const float*)d_in[0];
    }
    float* out = (float*)d_out;

    static bool attr_set = false;
    if (!attr_set) {
        cudaFuncSetAttribute(k_build, cudaFuncAttributeMaxDynamicSharedMemorySize,
                             SMEM_BUILD);
        attr_set = true;
    }

    k_build<<<NB, BTH, SMEM_BUILD>>>(src);
    k_query<<<(NB * NTGT) / 8, 256>>>(src, tgt, out);
}

// round 17
// speedup vs baseline: 2.8077x; 1.3566x over previous
#include <cuda_runtime.h>
#include <cstdint>
#include <cstddef>

#define NB    4
#define NSRC  16384
#define NTGT  4096
#define KNN   32
#define FULLM 0xffffffffu

// spatial grid
#define G     32
#define NCELL (G*G*G)
#define LB    6.0f
#define GH    0.375f
#define INVH  (1.0f/GH)

// scan kernel: padded smem histogram (conflict-free chunked scan)
#define BTH        1024
#define CPTW       (NCELL / BTH)       // 32 cells per thread
#define LPT        (NCELL / BTH)       // 32 coalesced loads per thread
#define NPAD       (NCELL + NCELL / 32)
#define PADI(i)    ((i) + ((i) >> 5))
#define SMEM_SCAN  ((NPAD + BTH) * (int)sizeof(int))

// Output layout (flattened concat, all float32):
#define OFF_PATCH 0
#define OFF_IDX   1572864
#define OFF_SIZE  2621440
#define OFF_RAD   2637824
#define OFF_DIST  2637828

// __device__ scratch (no allocations allowed). g_cnt zero-initialized at load
// and re-zeroed by k_scan each iteration (coalesced, free).
__device__ int    g_cnt[NB * NCELL];
__device__ int    g_cur[NB * NCELL];
__device__ int    g_start[NB * (NCELL + 1)];
__device__ float4 g_pts[NB * NSRC];   // (x, y, z, sumsq), cell-sorted
__device__ int    g_pidx[NB * NSRC];  // original within-batch index

__device__ __forceinline__ int cellcoord(float v) {
    int c = (int)floorf((v + LB) * INVH);
    return min(G - 1, max(0, c));
}

// distance from p to cell slab along one axis; boundary cells unbounded outward
__device__ __forceinline__ float axdist(float p, int i) {
    float lo = (i == 0)     ? -1e30f : __fmaf_rn((float)i, GH, -LB);
    float hi = (i == G - 1) ?  1e30f : __fmaf_rn((float)(i + 1), GH, -LB);
    return fmaxf(0.0f, fmaxf(lo - p, p - hi));
}

// count: 256 blocks, L2 atomics (atomic work spread across the whole chip)
__global__ void k_count(const float* __restrict__ src) {
    int i = blockIdx.x * blockDim.x + threadIdx.x;
    if (i >= NB * NSRC) return;
    int b = i / NSRC;
    float x = src[3 * i], y = src[3 * i + 1], z = src[3 * i + 2];
    int cell = (cellcoord(z) * G + cellcoord(y)) * G + cellcoord(x);
    atomicAdd(&g_cnt[b * NCELL + cell], 1);
}

// scan: one block per batch. Coalesced global IO; conflict-free padded smem.
__global__ __launch_bounds__(BTH) void k_scan() {
    extern __shared__ int smem[];
    int* scnt = smem;            // NPAD
    int* ssum = smem + NPAD;     // BTH

    const int b = blockIdx.x;
    const int t = threadIdx.x;
    int* cntg = g_cnt + b * NCELL;

    // A) coalesced load histogram -> padded smem; re-zero g_cnt in-pass
    #pragma unroll
    for (int k = 0; k < LPT; k++) {
        const int i = t + k * BTH;
        scnt[PADI(i)] = cntg[i];   // lane-stride 1 -> conflict-free
        cntg[i] = 0;
    }
    __syncthreads();

    // B) chunked scan: thread t owns cells [t*CPTW, (t+1)*CPTW)
    int cnt[CPTW];
    int s = 0;
    #pragma unroll
    for (int c = 0; c < CPTW; c++) {
        cnt[c] = scnt[PADI(t * CPTW + c)];   // lane-stride 33 -> conflict-free
        s += cnt[c];
    }
    ssum[t] = s;
    __syncthreads();
    for (int off = 1; off < BTH; off <<= 1) {
        int v = (t >= off) ? ssum[t - off] : 0;
        __syncthreads();
        ssum[t] += v;
        __syncthreads();
    }
    int run = ssum[t] - s;
    #pragma unroll
    for (int c = 0; c < CPTW; c++) {
        const int id = t * CPTW + c;
        scnt[PADI(id)] = run;               // conflict-free write-back
        run += cnt[c];
    }
    __syncthreads();

    // C) coalesced store of start/cursor arrays
    int* gstart = g_start + b * (NCELL + 1);
    int* gcur   = g_cur + b * NCELL;
    #pragma unroll
    for (int k = 0; k < LPT; k++) {
        const int i = t + k * BTH;
        const int v = scnt[PADI(i)];
        gstart[i] = v;
        gcur[i]   = v;
    }
    if (t == BTH - 1) gstart[NCELL] = NSRC;
}

// scatter: 256 blocks, L2 atomics on the cursors
__global__ void k_scatter(const float* __restrict__ src) {
    int i = blockIdx.x * blockDim.x + threadIdx.x;
    if (i >= NB * NSRC) return;
    int b = i / NSRC;
    float x = src[3 * i], y = src[3 * i + 1], z = src[3 * i + 2];
    int cell = (cellcoord(z) * G + cellcoord(y)) * G + cellcoord(x);
    int pos = atomicAdd(&g_cur[b * NCELL + cell], 1);
    float ss = __fadd_rn(__fadd_rn(__fmul_rn(x, x), __fmul_rn(y, y)), __fmul_rn(z, z));
    g_pts [b * NSRC + pos] = make_float4(x, y, z, ss);
    g_pidx[b * NSRC + pos] = i - b * NSRC;
}

// One warp per target. Exact KNN: center cell first, then thr-pruned d=1
// neighbor cells, then row-pruned shells d>=2. Pruning margin strictly
// dominates all fp error; lex (value,index) order == jax top_k tie-break,
// scan-order invariant (so atomic scatter order is irrelevant).
__global__ __launch_bounds__(256) void k_query(const float* __restrict__ src,
                                               const float* __restrict__ tgt,
                                               float* __restrict__ out) {
    __shared__ int s_p0 [8][32];
    __shared__ int s_pre[8][32];

    const int w    = threadIdx.x >> 5;
    const int lane = threadIdx.x & 31;
    const int tg   = blockIdx.x * 8 + w;
    const int b    = tg / NTGT;

    const float px = tgt[3 * tg], py = tgt[3 * tg + 1], pz = tgt[3 * tg + 2];
    const float tt = __fadd_rn(__fadd_rn(__fmul_rn(px, px), __fmul_rn(py, py)),
                               __fmul_rn(pz, pz));

    const int cx = cellcoord(px), cy = cellcoord(py), cz = cellcoord(pz);
    float ex = fmaxf(fmaxf(-LB - px, px - LB), 0.0f);
    float ey = fmaxf(fmaxf(-LB - py, py - LB), 0.0f);
    float ez = fmaxf(fmaxf(-LB - pz, pz - LB), 0.0f);
    const float e = sqrtf(ex * ex + ey * ey + ez * ez);

    const float INF  = __int_as_float(0x7f800000);
    const int   IMAX = 0x7fffffff;
    float lv = INF; int li = IMAX;
    float thr_v = INF; int thr_i = IMAX;
    bool filled = false;

    const int*    cstart = g_start + b * (NCELL + 1);
    const float4* pts    = g_pts + b * NSRC;
    const int*    pidx   = g_pidx + b * NSRC;

    const int dmax = max(max(max(cx, G - 1 - cx), max(cy, G - 1 - cy)),
                         max(cz, G - 1 - cz));

    // ascending-lex bitonic sort of one (value,index) per lane
    auto sort32 = [&](float& v, int& ix) {
        #pragma unroll
        for (int kk = 2; kk <= 32; kk <<= 1) {
            #pragma unroll
            for (int j = kk >> 1; j > 0; j >>= 1) {
                const float ov = __shfl_xor_sync(FULLM, v, j);
                const int   oi = __shfl_xor_sync(FULLM, ix, j);
                const bool dirAsc = ((lane & kk) == 0);
                const bool otherLess = (ov < v) || (ov == v && oi < ix);
                const bool lower = (lane & j) == 0;
                const bool keepOther = lower ? (dirAsc ? otherLess : !otherLess)
                                             : (dirAsc ? !otherLess : otherLess);
                if (keepOther) { v = ov; ix = oi; }
            }
        }
    };

    // consume one warp-batch (hybrid serial / batch-merge), lex order
    auto consume = [&](float sqv, int jj) {
        if (filled) {
            const bool acc = (sqv < thr_v) || (sqv == thr_v && jj < thr_i);
            unsigned ball = __ballot_sync(FULLM, acc);
            const int nacc = __popc(ball);
            if (nacc == 0) return;
            if (nacc < 8) {
                do {
                    const int   sl = __ffs(ball) - 1;
                    ball &= ball - 1;
                    const float nv = __shfl_sync(FULLM, sqv, sl);
                    const int   nj = __shfl_sync(FULLM, jj,  sl);
                    const unsigned le =
                        __ballot_sync(FULLM, (lv < nv) || (lv == nv && li < nj));
                    const int ppos = __popc(le);
                    if (ppos < 32) {
                        const float pv = __shfl_up_sync(FULLM, lv, 1);
                        const int   pj = __shfl_up_sync(FULLM, li, 1);
                        if (lane > ppos)       { lv = pv; li = pj; }
                        else if (lane == ppos) { lv = nv; li = nj; }
                    }
                } while (ball);
                thr_v = __shfl_sync(FULLM, lv, 31);
                thr_i = __shfl_sync(FULLM, li, 31);
                return;
            }
            if (!acc) { sqv = INF; jj = IMAX; }
            sort32(sqv, jj);
            const float bv = __shfl_sync(FULLM, sqv, 31 - lane);
            const int   bi = __shfl_sync(FULLM, jj,  31 - lane);
            const bool keepB = (bv < lv) || (bv == lv && bi < li);
            float cv = keepB ? bv : lv;
            int   ci = keepB ? bi : li;
            #pragma unroll
            for (int j = 16; j; j >>= 1) {
                const float ov = __shfl_xor_sync(FULLM, cv, j);
                const int   oi = __shfl_xor_sync(FULLM, ci, j);
                const bool otherLess = (ov < cv) || (ov == cv && oi < ci);
                const bool lower = (lane & j) == 0;
                if (lower ? otherLess : !otherLess) { cv = ov; ci = oi; }
            }
            lv = cv; li = ci;
            thr_v = __shfl_sync(FULLM, lv, 31);
            thr_i = __shfl_sync(FULLM, li, 31);
        } else {
            sort32(sqv, jj);
            lv = sqv; li = jj;
            thr_v = __shfl_sync(FULLM, lv, 31);
            thr_i = __shfl_sync(FULLM, li, 31);
            filled = true;
        }
    };

    auto evalP = [&](int ii, float& sqv, int& jj) {
        const float4 S = pts[ii];
        jj = pidx[ii];
        float dot = __fmaf_rn(pz, S.z, __fmaf_rn(py, S.y, __fmul_rn(px, S.x)));
        sqv = __fadd_rn(__fsub_rn(tt, __fmul_rn(2.0f, dot)), S.w);
    };

    // ---- d=0: center cell, contiguous (no search) ----
    {
        const int cell = (cz * G + cy) * G + cx;
        const int p0c = cstart[cell], p1c = cstart[cell + 1];
        for (int base = p0c; base < p1c; base += 32) {
            const int ii = base + lane;
            float sqv = INF; int jj = IMAX;
            if (ii < p1c) evalP(ii, sqv, jj);
            consume(sqv, jj);
        }
    }

    // ---- d=1: 26 neighbor cells, thr-pruned by box distance ----
    {
        int p0 = 0, len = 0;
        if (lane < 26) {
            const int k26 = lane + (lane >= 13);   // skip center (13)
            const int dx = k26 % 3 - 1;
            const int dy = (k26 / 3) % 3 - 1;
            const int dz = k26 / 9 - 1;
            const int xc = cx + dx, yc = cy + dy, zc = cz + dz;
            if (xc >= 0 && xc < G && yc >= 0 && yc < G && zc >= 0 && zc < G) {
                const float dmx = axdist(px, xc);
                const float dmy = axdist(py, yc);
                const float dmz = axdist(pz, zc);
                const float sq_lb = dmx * dmx + dmy * dmy + dmz * dmz;
                // conservative: margin >> all fp error; ties can't be lost
                if (!(sq_lb * 0.999f - 1e-4f > thr_v)) {
                    const int cell = (zc * G + yc) * G + xc;
                    p0  = cstart[cell];
                    len = cstart[cell + 1] - p0;
                }
            }
        }
        int pre = len;
        #pragma unroll
        for (int off = 1; off < 32; off <<= 1) {
            int n = __shfl_up_sync(FULLM, pre, off);
            if (lane >= off) pre += n;
        }
        const int total = __shfl_sync(FULLM, pre, 31);
        pre -= len;
        s_p0 [w][lane] = p0;
        s_pre[w][lane] = pre;
        __syncwarp(FULLM);

        for (int base = 0; base < total; base += 32) {
            const int pos = base + lane;
            float sqv = INF; int jj = IMAX;
            if (pos < total) {
                int lo = 0;
                #pragma unroll
                for (int step = 16; step; step >>= 1) {
                    const int cand = lo + step;
                    if (cand < 32 && s_pre[w][cand] <= pos) lo = cand;
                }
                evalP(s_p0[w][lo] + (pos - s_pre[w][lo]), sqv, jj);
            }
            consume(sqv, jj);
        }
    }

    // ---- shells d >= 2 (rare), row-pruned ----
    for (int d = 1;;) {
        const float dm = __fmaf_rn((float)d, GH, -e);
        if (dm > 0.0f && thr_v < dm * dm) break;   // strict: protects index ties
        if (d >= dmax) break;
        ++d;
        const int nseg = 8 * d + 2 * (2 * d - 1) * (2 * d - 1);
        for (int bk = 0; bk < nseg; bk += 32) {
            const int k = bk + lane;
            bool valid = (k < nseg);
            int zc = cz, yc = cy, x0 = cx, x1 = cx;
            bool inner = false;
            if (valid) {
                if (k < 8 * d) {                  // perimeter rows (full span)
                    const int side = k / (2 * d), off = k % (2 * d);
                    int zo, yo;
                    if      (side == 0) { zo = -d; yo = -d + off; }
                    else if (side == 1) { yo =  d; zo = -d + off; }
                    else if (side == 2) { zo =  d; yo =  d - off; }
                    else                { yo = -d; zo =  d - off; }
                    zc = cz + zo; yc = cy + yo;
                    x0 = max(cx - d, 0); x1 = min(cx + d, G - 1);
                } else {                           // inner rows: 2 single cells
                    const int k2 = k - 8 * d;
                    const int w2 = 2 * d - 1;
                    const int r = k2 >> 1, side2 = k2 & 1;
                    zc = cz + (-d + 1 + r / w2);
                    yc = cy + (-d + 1 + r % w2);
                    const int x = side2 ? (cx + d) : (cx - d);
                    x0 = x1 = x;
                    inner = true;
                    if (x < 0 || x >= G) valid = false;
                }
                if (zc < 0 || zc >= G || yc < 0 || yc >= G) valid = false;
            }
            if (valid) {
                const float dmy = axdist(py, yc);
                const float dmz = axdist(pz, zc);
                float sq_lb = dmy * dmy + dmz * dmz;
                if (inner) {
                    const float dmx = axdist(px, x0);
                    sq_lb += dmx * dmx;
                }
                if (sq_lb * 0.999f - 1e-4f > thr_v) valid = false;
            }
            int p0 = 0, len = 0;
            if (valid) {
                const int cb = (zc * G + yc) * G;
                p0  = cstart[cb + x0];
                len = cstart[cb + x1 + 1] - p0;
            }
            int pre = len;
            #pragma unroll
            for (int off = 1; off < 32; off <<= 1) {
                int n = __shfl_up_sync(FULLM, pre, off);
                if (lane >= off) pre += n;
            }
            const int total = __shfl_sync(FULLM, pre, 31);
            pre -= len;
            s_p0 [w][lane] = p0;
            s_pre[w][lane] = pre;
            __syncwarp(FULLM);
            if (total == 0) continue;

            for (int base = 0; base < total; base += 32) {
                const int pos = base + lane;
                float sqv = INF; int jj = IMAX;
                if (pos < total) {
                    int lo = 0;
                    #pragma unroll
                    for (int step = 16; step; step >>= 1) {
                        const int cand = lo + step;
                        if (cand < 32 && s_pre[w][cand] <= pos) lo = cand;
                    }
                    evalP(s_p0[w][lo] + (pos - s_pre[w][lo]), sqv, jj);
                }
                consume(sqv, jj);
            }
        }
    }

    // ---- outputs ----
    const float rad  = 0.2f;
    const float rad2 = __fmul_rn(rad, rad);
    const bool  mask = (rad2 >= lv);

    float gx = 0.0f, gy = 0.0f, gz = 0.0f;
    if (mask) {
        const float* sp = src + (size_t)(b * NSRC + li) * 3;
        gx = __fdiv_rn(sp[0], rad);
        gy = __fdiv_rn(sp[1], rad);
        gz = __fdiv_rn(sp[2], rad);
    }
    const float tdx = __fdiv_rn(px, rad);
    const float tdy = __fdiv_rn(py, rad);
    const float tdz = __fdiv_rn(pz, rad);

    const size_t ee = (size_t)tg * KNN + lane;

    float* patches = out + OFF_PATCH;
    patches[3 * ee + 0] = __fsub_rn(gx, tdx);
    patches[3 * ee + 1] = __fsub_rn(gy, tdy);
    patches[3 * ee + 2] = __fsub_rn(gz, tdz);

    float* idxf = out + OFF_IDX;
    idxf[2 * ee + 0] = (float)b;
    idxf[2 * ee + 1] = (float)(mask ? li : -1);

    float* pdist = out + OFF_DIST;
    pdist[ee] = __fdiv_rn(__fsqrt_rn(fmaxf(lv, 1e-9f)), rad);

    const unsigned mball = __ballot_sync(FULLM, mask);
    if (lane == 0) {
        float* psize = out + OFF_SIZE;
        psize[tg] = (float)__popc(mball);
    }

    if (blockIdx.x == 0 && threadIdx.x < NB) {
        float* prad = out + OFF_RAD;
        prad[threadIdx.x] = rad;
    }
}

extern "C" void kernel_launch(void* const* d_in, const int* in_sizes, int n_in,
                              void* d_out, int out_size) {
    const float* src = (const float*)d_in[0];
    const float* tgt = (const float*)d_in[1];
    if (n_in >= 2 && in_sizes[0] == NB * NTGT * 3 && in_sizes[1] == NB * NSRC * 3) {
        src = (const float*)d_in[1];
        tgt = (const float*)d_in[0];
    }
    float* out = (float*)d_out;

    static bool attr_set = false;
    if (!attr_set) {
        cudaFuncSetAttribute(k_scan, cudaFuncAttributeMaxDynamicSharedMemorySize,
                             SMEM_SCAN);
        attr_set = true;
    }

    k_count  <<<(NB * NSRC + 255) / 256, 256>>>(src);
    k_scan   <<<NB, BTH, SMEM_SCAN>>>();
    k_scatter<<<(NB * NSRC + 255) / 256, 256>>>(src);
    k_query  <<<(NB * NTGT) / 8, 256>>>(src, tgt, out);
}